// round 12
// baseline (speedup 1.0000x reference)
#include <cuda_runtime.h>
#include <cuda_bf16.h>
#include <cstdint>
#include <math.h>

// Problem constants: B=4, S=1024, D=1024, H=16, DH=64
// head-major scratch: [which(6)][b(4)][h(16)][s(1024)][d(64)], bf16 hi/lo split
__device__ __nv_bfloat16 g_qkv_hi[6ull * 4 * 16 * 1024 * 64];
__device__ __nv_bfloat16 g_qkv_lo[6ull * 4 * 16 * 1024 * 64];
// bf16 split GEMM operands
__device__ __nv_bfloat16 g_xhi[4096ull * 1024];
__device__ __nv_bfloat16 g_xlo[4096ull * 1024];
// W transposed to [which][n][k] so B tiles are K-major
__device__ __nv_bfloat16 g_wthi[6ull * 1024 * 1024];
__device__ __nv_bfloat16 g_wtlo[6ull * 1024 * 1024];

struct WPack {
    const float* W[6];
    const float* b[6];
};

// Side stream + events for graph-forked overlap. Created at static-init time
// (before the harness's memory checkpoints), reused every call; no per-call
// resource creation, so captured work is identical on every call.
static cudaStream_t g_s1 = [] { cudaStream_t s; cudaStreamCreateWithFlags(&s, cudaStreamNonBlocking); return s; }();
static cudaEvent_t g_e1 = [] { cudaEvent_t e; cudaEventCreateWithFlags(&e, cudaEventDisableTiming); return e; }();
static cudaEvent_t g_e2 = [] { cudaEvent_t e; cudaEventCreateWithFlags(&e, cudaEventDisableTiming); return e; }();

// ---------------------------------------------------------------------------
// mma / ldmatrix / cp.async helpers (sm_80+ portable; target is sm_100)
// ---------------------------------------------------------------------------
__device__ __forceinline__ uint32_t smem_u32(const void* p) {
    uint32_t a;
    asm("{ .reg .u64 t; cvta.to.shared.u64 t, %1; cvt.u32.u64 %0, t; }" : "=r"(a) : "l"(p));
    return a;
}

#define LDSM_X4(r0, r1, r2, r3, addr) \
    asm volatile("ldmatrix.sync.aligned.m8n8.x4.shared.b16 {%0,%1,%2,%3}, [%4];" \
                 : "=r"(r0), "=r"(r1), "=r"(r2), "=r"(r3) : "r"(addr))
#define LDSM_X4_T(r0, r1, r2, r3, addr) \
    asm volatile("ldmatrix.sync.aligned.m8n8.x4.trans.shared.b16 {%0,%1,%2,%3}, [%4];" \
                 : "=r"(r0), "=r"(r1), "=r"(r2), "=r"(r3) : "r"(addr))

#define MMA_BF16(d, a, b0_, b1_) \
    asm volatile("mma.sync.aligned.m16n8k16.row.col.f32.bf16.bf16.f32 " \
                 "{%0,%1,%2,%3}, {%4,%5,%6,%7}, {%8,%9}, {%0,%1,%2,%3};" \
                 : "+f"((d)[0]), "+f"((d)[1]), "+f"((d)[2]), "+f"((d)[3]) \
                 : "r"((a)[0]), "r"((a)[1]), "r"((a)[2]), "r"((a)[3]), "r"(b0_), "r"(b1_))

#define CP_ASYNC16(dst, src) \
    asm volatile("cp.async.cg.shared.global [%0], [%1], 16;" :: "r"(dst), "l"(src) : "memory")
#define CP_COMMIT() asm volatile("cp.async.commit_group;" ::: "memory")
#define CP_WAIT(N)  asm volatile("cp.async.wait_group %0;" :: "n"(N) : "memory")

__device__ __forceinline__ uint32_t pack_bf16x2(float a, float b) {
    __nv_bfloat162 t = __floats2bfloat162_rn(a, b);
    return *reinterpret_cast<uint32_t*>(&t);
}

// 64-col bf16 tile (128B rows), XOR-chunk swizzle. col must be a multiple of 8.
__device__ __forceinline__ uint32_t swz64(int r, int col) {
    return (uint32_t)((r << 7) + ((((col >> 3) ^ (r & 7)) << 4)));
}

// ---------------------------------------------------------------------------
// Convert X -> bf16 hi/lo (x4 vectorized)
// ---------------------------------------------------------------------------
__global__ __launch_bounds__(256) void convert_x_kernel(const float* __restrict__ x)
{
    int i = (blockIdx.x * 256 + threadIdx.x) * 4;
    float4 v = *reinterpret_cast<const float4*>(x + i);
    float f[4] = {v.x, v.y, v.z, v.w};
    __nv_bfloat16 h[4];
    float l[4];
#pragma unroll
    for (int e = 0; e < 4; e++) {
        h[e] = __float2bfloat16(f[e]);
        l[e] = f[e] - __bfloat162float(h[e]);
    }
    __nv_bfloat162 h01; h01.x = h[0]; h01.y = h[1];
    __nv_bfloat162 h23; h23.x = h[2]; h23.y = h[3];
    uint2 hw = make_uint2(*reinterpret_cast<uint32_t*>(&h01), *reinterpret_cast<uint32_t*>(&h23));
    uint2 lw = make_uint2(pack_bf16x2(l[0], l[1]), pack_bf16x2(l[2], l[3]));
    *reinterpret_cast<uint2*>(g_xhi + i) = hw;
    *reinterpret_cast<uint2*>(g_xlo + i) = lw;
}

// ---------------------------------------------------------------------------
// Convert + transpose W[k][n] -> Wt[n][k] bf16 hi/lo
// ---------------------------------------------------------------------------
__global__ __launch_bounds__(256) void convert_w_kernel(WPack wp)
{
    __shared__ float tile[32][33];
    const int w = blockIdx.z;
    const int n0 = blockIdx.x * 32;
    const int k0 = blockIdx.y * 32;
    const float* __restrict__ W = wp.W[w];
    const int tx = threadIdx.x;   // 0..31
    const int ty = threadIdx.y;   // 0..7
#pragma unroll
    for (int i = 0; i < 4; i++) {
        int k = k0 + ty + i * 8;
        tile[ty + i * 8][tx] = W[(size_t)k * 1024 + n0 + tx];
    }
    __syncthreads();
#pragma unroll
    for (int i = 0; i < 4; i++) {
        int n = n0 + ty + i * 8;
        float v = tile[tx][ty + i * 8];
        __nv_bfloat16 hi = __float2bfloat16(v);
        __nv_bfloat16 lo = __float2bfloat16(v - __bfloat162float(hi));
        size_t off = (size_t)w * 1048576 + (size_t)n * 1024 + k0 + tx;
        g_wthi[off] = hi;
        g_wtlo[off] = lo;
    }
}

// ---------------------------------------------------------------------------
// Zero-fill output (so attention streams can atomicAdd).
// ---------------------------------------------------------------------------
__global__ __launch_bounds__(256) void zero_out_kernel(float* __restrict__ out)
{
    int i = (blockIdx.x * 256 + threadIdx.x) * 4;
    *reinterpret_cast<float4*>(out + i) = make_float4(0.f, 0.f, 0.f, 0.f);
}

// ---------------------------------------------------------------------------
// HMMA projection GEMM — round-6 configuration (best measured): 256 thr,
// 8 warps (2x4), warp tile 64x32, 2-stage cp.async, 2 CTAs/SM.
// bn0 selects the N-range so the launch can be split per attention stream.
// ---------------------------------------------------------------------------
__global__ __launch_bounds__(256) void qkv_gemm_mma(WPack wp, int bn0)
{
    extern __shared__ char dsm[];
    const uint32_t sb = smem_u32(dsm);

    const int tid = threadIdx.x;
    const int lane = tid & 31;
    const int wid = tid >> 5;
    const int wm = wid >> 2;        // 0..1  -> 64-row half
    const int wn = wid & 3;         // 0..3  -> 32-col quarter
    const int bn = bn0 + blockIdx.x;
    const int bm = blockIdx.y;      // 0..31

    const __nv_bfloat16* __restrict__ ah = g_xhi + (size_t)(bm * 128) * 1024;
    const __nv_bfloat16* __restrict__ al = g_xlo + (size_t)(bm * 128) * 1024;
    const __nv_bfloat16* __restrict__ bhp = g_wthi + (size_t)(bn * 128) * 1024;
    const __nv_bfloat16* __restrict__ blp = g_wtlo + (size_t)(bn * 128) * 1024;

    auto issue = [&](int kb, int st) {
        uint32_t stb = sb + st * 40960;
#pragma unroll
        for (int uu = 0; uu < 2; uu++) {
            int idx = tid + uu * 256;           // 0..511
            int r = idx >> 2, c = idx & 3;
            size_t go = (size_t)r * 1024 + kb * 32 + c * 8;
            uint32_t so = (uint32_t)(r * 80 + c * 16);
            CP_ASYNC16(stb + so,          ah + go);
            CP_ASYNC16(stb + 10240 + so,  al + go);
            CP_ASYNC16(stb + 20480 + so,  bhp + go);
            CP_ASYNC16(stb + 30720 + so,  blp + go);
        }
    };

    float acc[4][4][4];
#pragma unroll
    for (int i = 0; i < 4; i++)
#pragma unroll
        for (int j = 0; j < 4; j++)
#pragma unroll
            for (int q = 0; q < 4; q++) acc[i][j][q] = 0.f;

    const int rsel = lane & 15;
    const int ksel = 8 * (lane >> 4);

    issue(0, 0); CP_COMMIT();
    issue(1, 1); CP_COMMIT();

    for (int kb = 0; kb < 32; kb++) {
        const int st = kb & 1;
        if (kb < 30) { CP_WAIT(1); } else { CP_WAIT(0); }
        __syncthreads();

        const uint32_t stb = sb + st * 40960;
#pragma unroll
        for (int ks = 0; ks < 2; ks++) {
            const uint32_t kk2 = (uint32_t)((ks * 16 + ksel) * 2);
            uint32_t bhf[4][2], blf[4][2];
#pragma unroll
            for (int np = 0; np < 2; np++) {
                uint32_t r0, r1, r2, r3;
                uint32_t adr = stb + 20480 + (uint32_t)((wn * 32 + np * 16 + rsel) * 80) + kk2;
                LDSM_X4(r0, r1, r2, r3, adr);
                bhf[2 * np][0] = r0; bhf[2 * np][1] = r2;
                bhf[2 * np + 1][0] = r1; bhf[2 * np + 1][1] = r3;
                LDSM_X4(r0, r1, r2, r3, adr + 10240);
                blf[2 * np][0] = r0; blf[2 * np][1] = r2;
                blf[2 * np + 1][0] = r1; blf[2 * np + 1][1] = r3;
            }
#pragma unroll
            for (int mt = 0; mt < 4; mt++) {
                uint32_t ahf[4], alf[4];
                uint32_t adr = stb + (uint32_t)((wm * 64 + mt * 16 + rsel) * 80) + kk2;
                LDSM_X4(ahf[0], ahf[1], ahf[2], ahf[3], adr);
                LDSM_X4(alf[0], alf[1], alf[2], alf[3], adr + 10240);
#pragma unroll
                for (int nt = 0; nt < 4; nt++) {
                    MMA_BF16(acc[mt][nt], ahf, bhf[nt][0], bhf[nt][1]);
                    MMA_BF16(acc[mt][nt], ahf, blf[nt][0], blf[nt][1]);
                    MMA_BF16(acc[mt][nt], alf, bhf[nt][0], bhf[nt][1]);
                }
            }
        }
        __syncthreads();
        if (kb + 2 < 32) { issue(kb + 2, st); CP_COMMIT(); }
    }

    // Epilogue: bias + bf16 hi/lo split, scattered to head-major layout
#pragma unroll
    for (int mt = 0; mt < 4; mt++) {
        int m0 = bm * 128 + wm * 64 + mt * 16 + (lane >> 2);
#pragma unroll
        for (int half = 0; half < 2; half++) {
            int m = m0 + half * 8;
            int bb = m >> 10, s = m & 1023;
#pragma unroll
            for (int nt = 0; nt < 4; nt++) {
                int ng = bn * 128 + wn * 32 + nt * 8 + 2 * (lane & 3);
                int which = ng >> 10, rem = ng & 1023;
                int hh = rem >> 6, d = rem & 63;
                float2 bias2 = *reinterpret_cast<const float2*>(wp.b[which] + rem);
                float v0 = acc[mt][nt][half * 2 + 0] + bias2.x;
                float v1 = acc[mt][nt][half * 2 + 1] + bias2.y;
                __nv_bfloat16 h0 = __float2bfloat16(v0);
                __nv_bfloat16 h1 = __float2bfloat16(v1);
                float l0 = v0 - __bfloat162float(h0);
                float l1 = v1 - __bfloat162float(h1);
                size_t off = (((size_t)which * 4 + bb) * 16 + hh) * 65536 + (size_t)s * 64 + d;
                __nv_bfloat162 hp; hp.x = h0; hp.y = h1;
                *reinterpret_cast<uint32_t*>(&g_qkv_hi[off]) = *reinterpret_cast<uint32_t*>(&hp);
                *reinterpret_cast<uint32_t*>(&g_qkv_lo[off]) = pack_bf16x2(l0, l1);
            }
        }
    }
}

// ---------------------------------------------------------------------------
// HMMA flash attention (round-6 geometry: q-tile 64, 4 warps, 2-stage
// cp.async). One launch per stream (type); both atomically accumulate into
// the zeroed output (2 commutative adds per element -> bit-deterministic,
// safe even when the two launches run concurrently on different streams).
// Dynamic smem: 2 stages x {Kh,Kl,Vh,Vl} 64x64 bf16 swizzled = 65536 B.
// ---------------------------------------------------------------------------
__global__ __launch_bounds__(128) void attn_mma(const float* __restrict__ attn_w,
                                                float* __restrict__ out, int type)
{
    extern __shared__ char dsm[];
    const uint32_t sb = smem_u32(dsm);

    const int tid = threadIdx.x;
    const int lane = tid & 31;
    const int warp = tid >> 5;
    const int qt = blockIdx.x;       // 0..15
    const int bhv = blockIdx.y;      // 0..63
    const int b = bhv >> 4, h = bhv & 15;

    const size_t base = ((size_t)b * 16 + h) * 65536;
    const __nv_bfloat16* __restrict__ qh = g_qkv_hi + (size_t)(type * 3 + 0) * 4194304 + base;
    const __nv_bfloat16* __restrict__ ql = g_qkv_lo + (size_t)(type * 3 + 0) * 4194304 + base;
    const __nv_bfloat16* __restrict__ kh = g_qkv_hi + (size_t)(type * 3 + 1) * 4194304 + base;
    const __nv_bfloat16* __restrict__ kl = g_qkv_lo + (size_t)(type * 3 + 1) * 4194304 + base;
    const __nv_bfloat16* __restrict__ vh = g_qkv_hi + (size_t)(type * 3 + 2) * 4194304 + base;
    const __nv_bfloat16* __restrict__ vl = g_qkv_lo + (size_t)(type * 3 + 2) * 4194304 + base;

    const int rsel = lane & 15;
    const int ksel = 8 * (lane >> 4);

    // ---- stage Q through stage-0 K buffers via cp.async, grab Q fragments ----
#pragma unroll
    for (int u = 0; u < 4; u++) {
        int idx = tid + u * 128;            // 0..511
        int r = idx >> 3, c = idx & 7;
        size_t go = (size_t)(qt * 64 + r) * 64 + c * 8;
        uint32_t so = swz64(r, c * 8);
        CP_ASYNC16(sb + so,        qh + go);
        CP_ASYNC16(sb + 8192 + so, ql + go);
    }
    CP_COMMIT();
    CP_WAIT(0);
    __syncthreads();

    uint32_t qfh[4][4], qfl[4][4];
#pragma unroll
    for (int ks = 0; ks < 4; ks++) {
        int kk = ks * 16 + ksel;
        uint32_t adr = sb + swz64(warp * 16 + rsel, kk);
        LDSM_X4(qfh[ks][0], qfh[ks][1], qfh[ks][2], qfh[ks][3], adr);
        LDSM_X4(qfl[ks][0], qfl[ks][1], qfl[ks][2], qfl[ks][3], adr + 8192);
    }
    __syncthreads();   // all warps done reading stage 0 before K/V prefetch

    // K/V prefetch: per stage/array 64 rows x 8 chunks; 4 chunks/thread
    auto issue_kv = [&](int kt, int st) {
        uint32_t stb = sb + st * 32768;
#pragma unroll
        for (int u = 0; u < 4; u++) {
            int idx = tid + u * 128;
            int r = idx >> 3, c = idx & 7;
            size_t go = (size_t)(kt * 64 + r) * 64 + c * 8;
            uint32_t so = swz64(r, c * 8);
            CP_ASYNC16(stb + so,         kh + go);
            CP_ASYNC16(stb + 8192 + so,  kl + go);
            CP_ASYNC16(stb + 16384 + so, vh + go);
            CP_ASYNC16(stb + 24576 + so, vl + go);
        }
    };

    issue_kv(0, 0); CP_COMMIT();
    issue_kv(1, 1); CP_COMMIT();

    float o[8][4];
#pragma unroll
    for (int i = 0; i < 8; i++)
#pragma unroll
        for (int j = 0; j < 4; j++) o[i][j] = 0.f;
    float M0 = -1e30f, M1 = -1e30f, L0 = 0.f, L1 = 0.f;

    for (int kt = 0; kt < 16; kt++) {
        const int st = kt & 1;
        if (kt < 14) { CP_WAIT(1); } else { CP_WAIT(0); }
        __syncthreads();
        const uint32_t stb = sb + st * 32768;

        // ---- S = Q K^T (16 x 64), 3-way split ----
        float s[8][4];
#pragma unroll
        for (int i = 0; i < 8; i++)
#pragma unroll
            for (int j = 0; j < 4; j++) s[i][j] = 0.f;

#pragma unroll
        for (int ks = 0; ks < 4; ks++) {
            const int kk = ks * 16 + ksel;
            uint32_t bhf[8][2], blf[8][2];
#pragma unroll
            for (int np = 0; np < 4; np++) {
                uint32_t r0, r1, r2, r3;
                uint32_t adr = stb + swz64(np * 16 + rsel, kk);
                LDSM_X4(r0, r1, r2, r3, adr);
                bhf[2 * np][0] = r0; bhf[2 * np][1] = r2;
                bhf[2 * np + 1][0] = r1; bhf[2 * np + 1][1] = r3;
                LDSM_X4(r0, r1, r2, r3, adr + 8192);
                blf[2 * np][0] = r0; blf[2 * np][1] = r2;
                blf[2 * np + 1][0] = r1; blf[2 * np + 1][1] = r3;
            }
#pragma unroll
            for (int nt = 0; nt < 8; nt++) {
                MMA_BF16(s[nt], qfh[ks], bhf[nt][0], bhf[nt][1]);
                MMA_BF16(s[nt], qfh[ks], blf[nt][0], blf[nt][1]);
                MMA_BF16(s[nt], qfl[ks], bhf[nt][0], bhf[nt][1]);
            }
        }

        // ---- online softmax (rows: lane/4 and lane/4+8; quad-lane reduce) ----
        float rm0 = -1e30f, rm1 = -1e30f;
#pragma unroll
        for (int nt = 0; nt < 8; nt++) {
#pragma unroll
            for (int j = 0; j < 4; j++) s[nt][j] *= 0.125f;
            rm0 = fmaxf(rm0, fmaxf(s[nt][0], s[nt][1]));
            rm1 = fmaxf(rm1, fmaxf(s[nt][2], s[nt][3]));
        }
        rm0 = fmaxf(rm0, __shfl_xor_sync(0xffffffffu, rm0, 1));
        rm0 = fmaxf(rm0, __shfl_xor_sync(0xffffffffu, rm0, 2));
        rm1 = fmaxf(rm1, __shfl_xor_sync(0xffffffffu, rm1, 1));
        rm1 = fmaxf(rm1, __shfl_xor_sync(0xffffffffu, rm1, 2));
        float mn0 = fmaxf(M0, rm0), mn1 = fmaxf(M1, rm1);
        float sc0 = __expf(M0 - mn0), sc1 = __expf(M1 - mn1);
        float rs0 = 0.f, rs1 = 0.f;
#pragma unroll
        for (int nt = 0; nt < 8; nt++) {
            s[nt][0] = __expf(s[nt][0] - mn0);
            s[nt][1] = __expf(s[nt][1] - mn0);
            s[nt][2] = __expf(s[nt][2] - mn1);
            s[nt][3] = __expf(s[nt][3] - mn1);
            rs0 += s[nt][0] + s[nt][1];
            rs1 += s[nt][2] + s[nt][3];
        }
        rs0 += __shfl_xor_sync(0xffffffffu, rs0, 1);
        rs0 += __shfl_xor_sync(0xffffffffu, rs0, 2);
        rs1 += __shfl_xor_sync(0xffffffffu, rs1, 1);
        rs1 += __shfl_xor_sync(0xffffffffu, rs1, 2);
        L0 = L0 * sc0 + rs0; M0 = mn0;
        L1 = L1 * sc1 + rs1; M1 = mn1;
#pragma unroll
        for (int dt = 0; dt < 8; dt++) {
            o[dt][0] *= sc0; o[dt][1] *= sc0;
            o[dt][2] *= sc1; o[dt][3] *= sc1;
        }

        // ---- pack P (hi/lo) into A fragments: accum->A register identity ----
        uint32_t ph[4][4], pl[4][4];
#pragma unroll
        for (int kp = 0; kp < 4; kp++) {
            const int t0 = 2 * kp, t1 = 2 * kp + 1;
            float p_[8] = {s[t0][0], s[t0][1], s[t0][2], s[t0][3],
                           s[t1][0], s[t1][1], s[t1][2], s[t1][3]};
            __nv_bfloat16 hb[8];
            float lb[8];
#pragma unroll
            for (int e = 0; e < 8; e++) {
                hb[e] = __float2bfloat16(p_[e]);
                lb[e] = p_[e] - __bfloat162float(hb[e]);
            }
            __nv_bfloat162 t;
            t.x = hb[0]; t.y = hb[1]; ph[kp][0] = *reinterpret_cast<uint32_t*>(&t);
            t.x = hb[2]; t.y = hb[3]; ph[kp][1] = *reinterpret_cast<uint32_t*>(&t);
            t.x = hb[4]; t.y = hb[5]; ph[kp][2] = *reinterpret_cast<uint32_t*>(&t);
            t.x = hb[6]; t.y = hb[7]; ph[kp][3] = *reinterpret_cast<uint32_t*>(&t);
            pl[kp][0] = pack_bf16x2(lb[0], lb[1]);
            pl[kp][1] = pack_bf16x2(lb[2], lb[3]);
            pl[kp][2] = pack_bf16x2(lb[4], lb[5]);
            pl[kp][3] = pack_bf16x2(lb[6], lb[7]);
        }

        // ---- O += P V  (V^T fragments via ldmatrix.trans) ----
        const int krow = ((lane >> 4) * 8) + (lane & 7);
        const int dcol = ((lane >> 3) & 1) * 8;
#pragma unroll
        for (int ks = 0; ks < 4; ks++) {
            uint32_t vhf[8][2], vlf[8][2];
#pragma unroll
            for (int dp = 0; dp < 4; dp++) {
                uint32_t r0, r1, r2, r3;
                uint32_t adr = stb + 16384 + swz64(ks * 16 + krow, dp * 16 + dcol);
                LDSM_X4_T(r0, r1, r2, r3, adr);
                vhf[2 * dp][0] = r0; vhf[2 * dp][1] = r2;
                vhf[2 * dp + 1][0] = r1; vhf[2 * dp + 1][1] = r3;
                LDSM_X4_T(r0, r1, r2, r3, adr + 8192);
                vlf[2 * dp][0] = r0; vlf[2 * dp][1] = r2;
                vlf[2 * dp + 1][0] = r1; vlf[2 * dp + 1][1] = r3;
            }
#pragma unroll
            for (int dt = 0; dt < 8; dt++) {
                MMA_BF16(o[dt], ph[ks], vhf[dt][0], vhf[dt][1]);
                MMA_BF16(o[dt], ph[ks], vlf[dt][0], vlf[dt][1]);
                MMA_BF16(o[dt], pl[ks], vhf[dt][0], vhf[dt][1]);
            }
        }
        __syncthreads();
        if (kt + 2 < 16) { issue_kv(kt + 2, st); CP_COMMIT(); }
    }

    // ---- finalize: divide by L, apply stream weight, atomically accumulate ----
    float w0a = attn_w[0], w1a = attn_w[1];
    float mx = fmaxf(w0a, w1a);
    float e0 = __expf(w0a - mx), e1 = __expf(w1a - mx);
    float wA = ((type == 0) ? e0 : e1) / (e0 + e1);
    float i0 = wA / L0, i1 = wA / L1;

    const int r0 = qt * 64 + warp * 16 + (lane >> 2);
#pragma unroll
    for (int dt = 0; dt < 8; dt++) {
        int col = h * 64 + dt * 8 + 2 * (lane & 3);
        float* p0 = out + ((size_t)b * 1024 + r0) * 1024 + col;
        float* p1 = out + ((size_t)b * 1024 + r0 + 8) * 1024 + col;
        atomicAdd(p0 + 0, o[dt][0] * i0);
        atomicAdd(p0 + 1, o[dt][1] * i0);
        atomicAdd(p1 + 0, o[dt][2] * i1);
        atomicAdd(p1 + 1, o[dt][3] * i1);
    }
}

// ---------------------------------------------------------------------------
// Launch: fork the graph so attn(stream 0) overlaps the second GEMM half.
//   s0: conv -> zero -> G1(which 0-2) -> [e1] -> G2(which 3-5) -> attn1 -> wait e2
//   s1:                        wait e1 -> attn0 -> [e2]
// ---------------------------------------------------------------------------
extern "C" void kernel_launch(void* const* d_in, const int* in_sizes, int n_in,
                              void* d_out, int out_size)
{
    (void)in_sizes; (void)n_in; (void)out_size;
    const float* x = (const float*)d_in[0];
    WPack wp;
    for (int i = 0; i < 6; i++) {
        wp.W[i] = (const float*)d_in[1 + 2 * i];
        wp.b[i] = (const float*)d_in[2 + 2 * i];
    }
    const float* attn_w = (const float*)d_in[13];
    float* out = (float*)d_out;

    const int GEMM_SMEM = 81920;   // 2 stages x 4 arrays x 128x40 bf16 (2 CTAs/SM)
    const int ATTN_SMEM = 65536;   // 2 stages x 4 arrays x 64x64 bf16 (swizzled)
    cudaFuncSetAttribute(qkv_gemm_mma, cudaFuncAttributeMaxDynamicSharedMemorySize, GEMM_SMEM);
    cudaFuncSetAttribute(attn_mma, cudaFuncAttributeMaxDynamicSharedMemorySize, ATTN_SMEM);

    // 1) conversions + output zero-fill
    convert_x_kernel<<<4096, 256>>>(x);
    convert_w_kernel<<<dim3(32, 32, 6), dim3(32, 8)>>>(wp);
    zero_out_kernel<<<4096, 256>>>(out);

    // 2) GEMM half 1: which 0..2 (bn 0..23)
    qkv_gemm_mma<<<dim3(24, 32), 256, GEMM_SMEM>>>(wp, 0);
    cudaEventRecord(g_e1, 0);

    // fork: attn stream-0 runs on side stream, overlapping GEMM half 2
    cudaStreamWaitEvent(g_s1, g_e1, 0);
    attn_mma<<<dim3(16, 64), 128, ATTN_SMEM, g_s1>>>(attn_w, out, 0);

    // 3) GEMM half 2: which 3..5 (bn 24..47), then attn stream-1
    qkv_gemm_mma<<<dim3(24, 32), 256, GEMM_SMEM>>>(wp, 24);
    attn_mma<<<dim3(16, 64), 128, ATTN_SMEM>>>(attn_w, out, 1);

    // join
    cudaEventRecord(g_e2, g_s1);
    cudaStreamWaitEvent(0, g_e2, 0);
}

// round 14
// speedup vs baseline: 1.0554x; 1.0554x over previous
#include <cuda_runtime.h>
#include <cuda_bf16.h>
#include <cstdint>
#include <math.h>

// Problem constants: B=4, S=1024, D=1024, H=16, DH=64
// head-major scratch: [which(6)][b(4)][h(16)][s(1024)][d(64)], bf16 hi/lo split
__device__ __nv_bfloat16 g_qkv_hi[6ull * 4 * 16 * 1024 * 64];
__device__ __nv_bfloat16 g_qkv_lo[6ull * 4 * 16 * 1024 * 64];
// bf16 split GEMM operands
__device__ __nv_bfloat16 g_xhi[4096ull * 1024];
__device__ __nv_bfloat16 g_xlo[4096ull * 1024];
// W transposed to [which][n][k] so B tiles are K-major
__device__ __nv_bfloat16 g_wthi[6ull * 1024 * 1024];
__device__ __nv_bfloat16 g_wtlo[6ull * 1024 * 1024];

struct WPack {
    const float* W[6];
    const float* b[6];
};

// ---------------------------------------------------------------------------
// mma / ldmatrix / cp.async helpers (sm_80+ portable; target is sm_100)
// ---------------------------------------------------------------------------
__device__ __forceinline__ uint32_t smem_u32(const void* p) {
    uint32_t a;
    asm("{ .reg .u64 t; cvta.to.shared.u64 t, %1; cvt.u32.u64 %0, t; }" : "=r"(a) : "l"(p));
    return a;
}

#define LDSM_X4(r0, r1, r2, r3, addr) \
    asm volatile("ldmatrix.sync.aligned.m8n8.x4.shared.b16 {%0,%1,%2,%3}, [%4];" \
                 : "=r"(r0), "=r"(r1), "=r"(r2), "=r"(r3) : "r"(addr))
#define LDSM_X4_T(r0, r1, r2, r3, addr) \
    asm volatile("ldmatrix.sync.aligned.m8n8.x4.trans.shared.b16 {%0,%1,%2,%3}, [%4];" \
                 : "=r"(r0), "=r"(r1), "=r"(r2), "=r"(r3) : "r"(addr))

#define MMA_BF16(d, a, b0_, b1_) \
    asm volatile("mma.sync.aligned.m16n8k16.row.col.f32.bf16.bf16.f32 " \
                 "{%0,%1,%2,%3}, {%4,%5,%6,%7}, {%8,%9}, {%0,%1,%2,%3};" \
                 : "+f"((d)[0]), "+f"((d)[1]), "+f"((d)[2]), "+f"((d)[3]) \
                 : "r"((a)[0]), "r"((a)[1]), "r"((a)[2]), "r"((a)[3]), "r"(b0_), "r"(b1_))

#define CP_ASYNC16(dst, src) \
    asm volatile("cp.async.cg.shared.global [%0], [%1], 16;" :: "r"(dst), "l"(src) : "memory")
#define CP_COMMIT() asm volatile("cp.async.commit_group;" ::: "memory")
#define CP_WAIT(N)  asm volatile("cp.async.wait_group %0;" :: "n"(N) : "memory")

__device__ __forceinline__ uint32_t pack_bf16x2(float a, float b) {
    __nv_bfloat162 t = __floats2bfloat162_rn(a, b);
    return *reinterpret_cast<uint32_t*>(&t);
}

// 64-col bf16 tile (128B rows), XOR-chunk swizzle. col must be a multiple of 8.
__device__ __forceinline__ uint32_t swz64(int r, int col) {
    return (uint32_t)((r << 7) + ((((col >> 3) ^ (r & 7)) << 4)));
}

// ---------------------------------------------------------------------------
// Convert X -> bf16 hi/lo (x4 vectorized) + zero-fill output (same extent:
// both are 4M elements; fusing removes a launch).
// ---------------------------------------------------------------------------
__global__ __launch_bounds__(256) void convert_x_kernel(const float* __restrict__ x,
                                                        float* __restrict__ out)
{
    int i = (blockIdx.x * 256 + threadIdx.x) * 4;
    float4 v = *reinterpret_cast<const float4*>(x + i);
    float f[4] = {v.x, v.y, v.z, v.w};
    __nv_bfloat16 h[4];
    float l[4];
#pragma unroll
    for (int e = 0; e < 4; e++) {
        h[e] = __float2bfloat16(f[e]);
        l[e] = f[e] - __bfloat162float(h[e]);
    }
    __nv_bfloat162 h01; h01.x = h[0]; h01.y = h[1];
    __nv_bfloat162 h23; h23.x = h[2]; h23.y = h[3];
    uint2 hw = make_uint2(*reinterpret_cast<uint32_t*>(&h01), *reinterpret_cast<uint32_t*>(&h23));
    uint2 lw = make_uint2(pack_bf16x2(l[0], l[1]), pack_bf16x2(l[2], l[3]));
    *reinterpret_cast<uint2*>(g_xhi + i) = hw;
    *reinterpret_cast<uint2*>(g_xlo + i) = lw;
    *reinterpret_cast<float4*>(out + i) = make_float4(0.f, 0.f, 0.f, 0.f);
}

// ---------------------------------------------------------------------------
// Convert + transpose W[k][n] -> Wt[n][k] bf16 hi/lo
// ---------------------------------------------------------------------------
__global__ __launch_bounds__(256) void convert_w_kernel(WPack wp)
{
    __shared__ float tile[32][33];
    const int w = blockIdx.z;
    const int n0 = blockIdx.x * 32;
    const int k0 = blockIdx.y * 32;
    const float* __restrict__ W = wp.W[w];
    const int tx = threadIdx.x;   // 0..31
    const int ty = threadIdx.y;   // 0..7
#pragma unroll
    for (int i = 0; i < 4; i++) {
        int k = k0 + ty + i * 8;
        tile[ty + i * 8][tx] = W[(size_t)k * 1024 + n0 + tx];
    }
    __syncthreads();
#pragma unroll
    for (int i = 0; i < 4; i++) {
        int n = n0 + ty + i * 8;
        float v = tile[tx][ty + i * 8];
        __nv_bfloat16 hi = __float2bfloat16(v);
        __nv_bfloat16 lo = __float2bfloat16(v - __bfloat162float(hi));
        size_t off = (size_t)w * 1048576 + (size_t)n * 1024 + k0 + tx;
        g_wthi[off] = hi;
        g_wtlo[off] = lo;
    }
}

// ---------------------------------------------------------------------------
// HMMA projection GEMM — EXACT round-6 configuration (best measured):
// 256 thr, 8 warps (2x4), warp tile 64x32, 2-stage cp.async, issue AFTER
// compute, two barriers per iteration. smem 81920 B -> 2 CTAs/SM.
// ---------------------------------------------------------------------------
__global__ __launch_bounds__(256) void qkv_gemm_mma(WPack wp)
{
    extern __shared__ char dsm[];
    const uint32_t sb = smem_u32(dsm);

    const int tid = threadIdx.x;
    const int lane = tid & 31;
    const int wid = tid >> 5;
    const int wm = wid >> 2;        // 0..1  -> 64-row half
    const int wn = wid & 3;         // 0..3  -> 32-col quarter
    const int bn = blockIdx.x;      // 0..47
    const int bm = blockIdx.y;      // 0..31

    const __nv_bfloat16* __restrict__ ah = g_xhi + (size_t)(bm * 128) * 1024;
    const __nv_bfloat16* __restrict__ al = g_xlo + (size_t)(bm * 128) * 1024;
    const __nv_bfloat16* __restrict__ bhp = g_wthi + (size_t)(bn * 128) * 1024;
    const __nv_bfloat16* __restrict__ blp = g_wtlo + (size_t)(bn * 128) * 1024;

    auto issue = [&](int kb, int st) {
        uint32_t stb = sb + st * 40960;
#pragma unroll
        for (int uu = 0; uu < 2; uu++) {
            int idx = tid + uu * 256;           // 0..511
            int r = idx >> 2, c = idx & 3;
            size_t go = (size_t)r * 1024 + kb * 32 + c * 8;
            uint32_t so = (uint32_t)(r * 80 + c * 16);
            CP_ASYNC16(stb + so,          ah + go);
            CP_ASYNC16(stb + 10240 + so,  al + go);
            CP_ASYNC16(stb + 20480 + so,  bhp + go);
            CP_ASYNC16(stb + 30720 + so,  blp + go);
        }
    };

    float acc[4][4][4];
#pragma unroll
    for (int i = 0; i < 4; i++)
#pragma unroll
        for (int j = 0; j < 4; j++)
#pragma unroll
            for (int q = 0; q < 4; q++) acc[i][j][q] = 0.f;

    const int rsel = lane & 15;
    const int ksel = 8 * (lane >> 4);

    issue(0, 0); CP_COMMIT();
    issue(1, 1); CP_COMMIT();

    for (int kb = 0; kb < 32; kb++) {
        const int st = kb & 1;
        if (kb < 30) { CP_WAIT(1); } else { CP_WAIT(0); }
        __syncthreads();

        const uint32_t stb = sb + st * 40960;
#pragma unroll
        for (int ks = 0; ks < 2; ks++) {
            const uint32_t kk2 = (uint32_t)((ks * 16 + ksel) * 2);
            uint32_t bhf[4][2], blf[4][2];
#pragma unroll
            for (int np = 0; np < 2; np++) {
                uint32_t r0, r1, r2, r3;
                uint32_t adr = stb + 20480 + (uint32_t)((wn * 32 + np * 16 + rsel) * 80) + kk2;
                LDSM_X4(r0, r1, r2, r3, adr);
                bhf[2 * np][0] = r0; bhf[2 * np][1] = r2;
                bhf[2 * np + 1][0] = r1; bhf[2 * np + 1][1] = r3;
                LDSM_X4(r0, r1, r2, r3, adr + 10240);
                blf[2 * np][0] = r0; blf[2 * np][1] = r2;
                blf[2 * np + 1][0] = r1; blf[2 * np + 1][1] = r3;
            }
#pragma unroll
            for (int mt = 0; mt < 4; mt++) {
                uint32_t ahf[4], alf[4];
                uint32_t adr = stb + (uint32_t)((wm * 64 + mt * 16 + rsel) * 80) + kk2;
                LDSM_X4(ahf[0], ahf[1], ahf[2], ahf[3], adr);
                LDSM_X4(alf[0], alf[1], alf[2], alf[3], adr + 10240);
#pragma unroll
                for (int nt = 0; nt < 4; nt++) {
                    MMA_BF16(acc[mt][nt], ahf, bhf[nt][0], bhf[nt][1]);
                    MMA_BF16(acc[mt][nt], ahf, blf[nt][0], blf[nt][1]);
                    MMA_BF16(acc[mt][nt], alf, bhf[nt][0], bhf[nt][1]);
                }
            }
        }
        __syncthreads();
        if (kb + 2 < 32) { issue(kb + 2, st); CP_COMMIT(); }
    }

    // Epilogue: bias + bf16 hi/lo split, scattered to head-major layout
#pragma unroll
    for (int mt = 0; mt < 4; mt++) {
        int m0 = bm * 128 + wm * 64 + mt * 16 + (lane >> 2);
#pragma unroll
        for (int half = 0; half < 2; half++) {
            int m = m0 + half * 8;
            int bb = m >> 10, s = m & 1023;
#pragma unroll
            for (int nt = 0; nt < 4; nt++) {
                int ng = bn * 128 + wn * 32 + nt * 8 + 2 * (lane & 3);
                int which = ng >> 10, rem = ng & 1023;
                int hh = rem >> 6, d = rem & 63;
                float2 bias2 = *reinterpret_cast<const float2*>(wp.b[which] + rem);
                float v0 = acc[mt][nt][half * 2 + 0] + bias2.x;
                float v1 = acc[mt][nt][half * 2 + 1] + bias2.y;
                __nv_bfloat16 h0 = __float2bfloat16(v0);
                __nv_bfloat16 h1 = __float2bfloat16(v1);
                float l0 = v0 - __bfloat162float(h0);
                float l1 = v1 - __bfloat162float(h1);
                size_t off = (((size_t)which * 4 + bb) * 16 + hh) * 65536 + (size_t)s * 64 + d;
                __nv_bfloat162 hp; hp.x = h0; hp.y = h1;
                *reinterpret_cast<uint32_t*>(&g_qkv_hi[off]) = *reinterpret_cast<uint32_t*>(&hp);
                *reinterpret_cast<uint32_t*>(&g_qkv_lo[off]) = pack_bf16x2(l0, l1);
            }
        }
    }
}

// ---------------------------------------------------------------------------
// HMMA flash attention (round-6 geometry: q-tile 64, 4 warps, 2-stage
// cp.async). Both streams in ONE launch via grid.z; results combined with
// atomicAdd into the zeroed output (2 commutative adds per element ->
// bit-deterministic).
// Dynamic smem: 2 stages x {Kh,Kl,Vh,Vl} 64x64 bf16 swizzled = 65536 B.
// ---------------------------------------------------------------------------
__global__ __launch_bounds__(128) void attn_mma(const float* __restrict__ attn_w,
                                                float* __restrict__ out)
{
    extern __shared__ char dsm[];
    const uint32_t sb = smem_u32(dsm);

    const int tid = threadIdx.x;
    const int lane = tid & 31;
    const int warp = tid >> 5;
    const int qt = blockIdx.x;       // 0..15
    const int bhv = blockIdx.y;      // 0..63
    const int type = blockIdx.z;     // 0..1 (attention stream)
    const int b = bhv >> 4, h = bhv & 15;

    const size_t base = ((size_t)b * 16 + h) * 65536;
    const __nv_bfloat16* __restrict__ qh = g_qkv_hi + (size_t)(type * 3 + 0) * 4194304 + base;
    const __nv_bfloat16* __restrict__ ql = g_qkv_lo + (size_t)(type * 3 + 0) * 4194304 + base;
    const __nv_bfloat16* __restrict__ kh = g_qkv_hi + (size_t)(type * 3 + 1) * 4194304 + base;
    const __nv_bfloat16* __restrict__ kl = g_qkv_lo + (size_t)(type * 3 + 1) * 4194304 + base;
    const __nv_bfloat16* __restrict__ vh = g_qkv_hi + (size_t)(type * 3 + 2) * 4194304 + base;
    const __nv_bfloat16* __restrict__ vl = g_qkv_lo + (size_t)(type * 3 + 2) * 4194304 + base;

    const int rsel = lane & 15;
    const int ksel = 8 * (lane >> 4);

    // ---- stage Q through stage-0 K buffers via cp.async, grab Q fragments ----
#pragma unroll
    for (int u = 0; u < 4; u++) {
        int idx = tid + u * 128;            // 0..511
        int r = idx >> 3, c = idx & 7;
        size_t go = (size_t)(qt * 64 + r) * 64 + c * 8;
        uint32_t so = swz64(r, c * 8);
        CP_ASYNC16(sb + so,        qh + go);
        CP_ASYNC16(sb + 8192 + so, ql + go);
    }
    CP_COMMIT();
    CP_WAIT(0);
    __syncthreads();

    uint32_t qfh[4][4], qfl[4][4];
#pragma unroll
    for (int ks = 0; ks < 4; ks++) {
        int kk = ks * 16 + ksel;
        uint32_t adr = sb + swz64(warp * 16 + rsel, kk);
        LDSM_X4(qfh[ks][0], qfh[ks][1], qfh[ks][2], qfh[ks][3], adr);
        LDSM_X4(qfl[ks][0], qfl[ks][1], qfl[ks][2], qfl[ks][3], adr + 8192);
    }
    __syncthreads();   // all warps done reading stage 0 before K/V prefetch

    // K/V prefetch: per stage/array 64 rows x 8 chunks; 4 chunks/thread
    auto issue_kv = [&](int kt, int st) {
        uint32_t stb = sb + st * 32768;
#pragma unroll
        for (int u = 0; u < 4; u++) {
            int idx = tid + u * 128;
            int r = idx >> 3, c = idx & 7;
            size_t go = (size_t)(kt * 64 + r) * 64 + c * 8;
            uint32_t so = swz64(r, c * 8);
            CP_ASYNC16(stb + so,         kh + go);
            CP_ASYNC16(stb + 8192 + so,  kl + go);
            CP_ASYNC16(stb + 16384 + so, vh + go);
            CP_ASYNC16(stb + 24576 + so, vl + go);
        }
    };

    issue_kv(0, 0); CP_COMMIT();
    issue_kv(1, 1); CP_COMMIT();

    float o[8][4];
#pragma unroll
    for (int i = 0; i < 8; i++)
#pragma unroll
        for (int j = 0; j < 4; j++) o[i][j] = 0.f;
    float M0 = -1e30f, M1 = -1e30f, L0 = 0.f, L1 = 0.f;

    for (int kt = 0; kt < 16; kt++) {
        const int st = kt & 1;
        if (kt < 14) { CP_WAIT(1); } else { CP_WAIT(0); }
        __syncthreads();
        const uint32_t stb = sb + st * 32768;

        // ---- S = Q K^T (16 x 64), 3-way split ----
        float s[8][4];
#pragma unroll
        for (int i = 0; i < 8; i++)
#pragma unroll
            for (int j = 0; j < 4; j++) s[i][j] = 0.f;

#pragma unroll
        for (int ks = 0; ks < 4; ks++) {
            const int kk = ks * 16 + ksel;
            uint32_t bhf[8][2], blf[8][2];
#pragma unroll
            for (int np = 0; np < 4; np++) {
                uint32_t r0, r1, r2, r3;
                uint32_t adr = stb + swz64(np * 16 + rsel, kk);
                LDSM_X4(r0, r1, r2, r3, adr);
                bhf[2 * np][0] = r0; bhf[2 * np][1] = r2;
                bhf[2 * np + 1][0] = r1; bhf[2 * np + 1][1] = r3;
                LDSM_X4(r0, r1, r2, r3, adr + 8192);
                blf[2 * np][0] = r0; blf[2 * np][1] = r2;
                blf[2 * np + 1][0] = r1; blf[2 * np + 1][1] = r3;
            }
#pragma unroll
            for (int nt = 0; nt < 8; nt++) {
                MMA_BF16(s[nt], qfh[ks], bhf[nt][0], bhf[nt][1]);
                MMA_BF16(s[nt], qfh[ks], blf[nt][0], blf[nt][1]);
                MMA_BF16(s[nt], qfl[ks], bhf[nt][0], bhf[nt][1]);
            }
        }

        // ---- online softmax (rows: lane/4 and lane/4+8; quad-lane reduce) ----
        float rm0 = -1e30f, rm1 = -1e30f;
#pragma unroll
        for (int nt = 0; nt < 8; nt++) {
#pragma unroll
            for (int j = 0; j < 4; j++) s[nt][j] *= 0.125f;
            rm0 = fmaxf(rm0, fmaxf(s[nt][0], s[nt][1]));
            rm1 = fmaxf(rm1, fmaxf(s[nt][2], s[nt][3]));
        }
        rm0 = fmaxf(rm0, __shfl_xor_sync(0xffffffffu, rm0, 1));
        rm0 = fmaxf(rm0, __shfl_xor_sync(0xffffffffu, rm0, 2));
        rm1 = fmaxf(rm1, __shfl_xor_sync(0xffffffffu, rm1, 1));
        rm1 = fmaxf(rm1, __shfl_xor_sync(0xffffffffu, rm1, 2));
        float mn0 = fmaxf(M0, rm0), mn1 = fmaxf(M1, rm1);
        float sc0 = __expf(M0 - mn0), sc1 = __expf(M1 - mn1);
        float rs0 = 0.f, rs1 = 0.f;
#pragma unroll
        for (int nt = 0; nt < 8; nt++) {
            s[nt][0] = __expf(s[nt][0] - mn0);
            s[nt][1] = __expf(s[nt][1] - mn0);
            s[nt][2] = __expf(s[nt][2] - mn1);
            s[nt][3] = __expf(s[nt][3] - mn1);
            rs0 += s[nt][0] + s[nt][1];
            rs1 += s[nt][2] + s[nt][3];
        }
        rs0 += __shfl_xor_sync(0xffffffffu, rs0, 1);
        rs0 += __shfl_xor_sync(0xffffffffu, rs0, 2);
        rs1 += __shfl_xor_sync(0xffffffffu, rs1, 1);
        rs1 += __shfl_xor_sync(0xffffffffu, rs1, 2);
        L0 = L0 * sc0 + rs0; M0 = mn0;
        L1 = L1 * sc1 + rs1; M1 = mn1;
#pragma unroll
        for (int dt = 0; dt < 8; dt++) {
            o[dt][0] *= sc0; o[dt][1] *= sc0;
            o[dt][2] *= sc1; o[dt][3] *= sc1;
        }

        // ---- pack P (hi/lo) into A fragments: accum->A register identity ----
        uint32_t ph[4][4], pl[4][4];
#pragma unroll
        for (int kp = 0; kp < 4; kp++) {
            const int t0 = 2 * kp, t1 = 2 * kp + 1;
            float p_[8] = {s[t0][0], s[t0][1], s[t0][2], s[t0][3],
                           s[t1][0], s[t1][1], s[t1][2], s[t1][3]};
            __nv_bfloat16 hb[8];
            float lb[8];
#pragma unroll
            for (int e = 0; e < 8; e++) {
                hb[e] = __float2bfloat16(p_[e]);
                lb[e] = p_[e] - __bfloat162float(hb[e]);
            }
            __nv_bfloat162 t;
            t.x = hb[0]; t.y = hb[1]; ph[kp][0] = *reinterpret_cast<uint32_t*>(&t);
            t.x = hb[2]; t.y = hb[3]; ph[kp][1] = *reinterpret_cast<uint32_t*>(&t);
            t.x = hb[4]; t.y = hb[5]; ph[kp][2] = *reinterpret_cast<uint32_t*>(&t);
            t.x = hb[6]; t.y = hb[7]; ph[kp][3] = *reinterpret_cast<uint32_t*>(&t);
            pl[kp][0] = pack_bf16x2(lb[0], lb[1]);
            pl[kp][1] = pack_bf16x2(lb[2], lb[3]);
            pl[kp][2] = pack_bf16x2(lb[4], lb[5]);
            pl[kp][3] = pack_bf16x2(lb[6], lb[7]);
        }

        // ---- O += P V  (V^T fragments via ldmatrix.trans) ----
        const int krow = ((lane >> 4) * 8) + (lane & 7);
        const int dcol = ((lane >> 3) & 1) * 8;
#pragma unroll
        for (int ks = 0; ks < 4; ks++) {
            uint32_t vhf[8][2], vlf[8][2];
#pragma unroll
            for (int dp = 0; dp < 4; dp++) {
                uint32_t r0, r1, r2, r3;
                uint32_t adr = stb + 16384 + swz64(ks * 16 + krow, dp * 16 + dcol);
                LDSM_X4_T(r0, r1, r2, r3, adr);
                vhf[2 * dp][0] = r0; vhf[2 * dp][1] = r2;
                vhf[2 * dp + 1][0] = r1; vhf[2 * dp + 1][1] = r3;
                LDSM_X4_T(r0, r1, r2, r3, adr + 8192);
                vlf[2 * dp][0] = r0; vlf[2 * dp][1] = r2;
                vlf[2 * dp + 1][0] = r1; vlf[2 * dp + 1][1] = r3;
            }
#pragma unroll
            for (int dt = 0; dt < 8; dt++) {
                MMA_BF16(o[dt], ph[ks], vhf[dt][0], vhf[dt][1]);
                MMA_BF16(o[dt], ph[ks], vlf[dt][0], vlf[dt][1]);
                MMA_BF16(o[dt], pl[ks], vhf[dt][0], vhf[dt][1]);
            }
        }
        __syncthreads();
        if (kt + 2 < 16) { issue_kv(kt + 2, st); CP_COMMIT(); }
    }

    // ---- finalize: divide by L, apply stream weight, atomically accumulate ----
    float w0a = attn_w[0], w1a = attn_w[1];
    float mx = fmaxf(w0a, w1a);
    float e0 = __expf(w0a - mx), e1 = __expf(w1a - mx);
    float wA = ((type == 0) ? e0 : e1) / (e0 + e1);
    float i0 = wA / L0, i1 = wA / L1;

    const int r0 = qt * 64 + warp * 16 + (lane >> 2);
#pragma unroll
    for (int dt = 0; dt < 8; dt++) {
        int col = h * 64 + dt * 8 + 2 * (lane & 3);
        float* p0 = out + ((size_t)b * 1024 + r0) * 1024 + col;
        float* p1 = out + ((size_t)b * 1024 + r0 + 8) * 1024 + col;
        atomicAdd(p0 + 0, o[dt][0] * i0);
        atomicAdd(p0 + 1, o[dt][1] * i0);
        atomicAdd(p1 + 0, o[dt][2] * i1);
        atomicAdd(p1 + 1, o[dt][3] * i1);
    }
}

// ---------------------------------------------------------------------------
// Launch: simple sequential stream. Best-measured variant of each component:
//   convert_x(+zero) -> convert_w -> GEMM (r6 exact) -> attn (merged, r9)
// ---------------------------------------------------------------------------
extern "C" void kernel_launch(void* const* d_in, const int* in_sizes, int n_in,
                              void* d_out, int out_size)
{
    (void)in_sizes; (void)n_in; (void)out_size;
    const float* x = (const float*)d_in[0];
    WPack wp;
    for (int i = 0; i < 6; i++) {
        wp.W[i] = (const float*)d_in[1 + 2 * i];
        wp.b[i] = (const float*)d_in[2 + 2 * i];
    }
    const float* attn_w = (const float*)d_in[13];
    float* out = (float*)d_out;

    const int GEMM_SMEM = 81920;   // 2 stages x 4 arrays x 128x40 bf16 (2 CTAs/SM)
    const int ATTN_SMEM = 65536;   // 2 stages x 4 arrays x 64x64 bf16 (swizzled)
    cudaFuncSetAttribute(qkv_gemm_mma, cudaFuncAttributeMaxDynamicSharedMemorySize, GEMM_SMEM);
    cudaFuncSetAttribute(attn_mma, cudaFuncAttributeMaxDynamicSharedMemorySize, ATTN_SMEM);

    // 1) conversions; output zero-fill fused into convert_x
    convert_x_kernel<<<4096, 256>>>(x, out);
    convert_w_kernel<<<dim3(32, 32, 6), dim3(32, 8)>>>(wp);

    // 2) HMMA projection GEMM (exact round-6 configuration)
    qkv_gemm_mma<<<dim3(48, 32), 256, GEMM_SMEM>>>(wp);

    // 3) HMMA flash attention, both streams in one launch (grid.z = 2)
    attn_mma<<<dim3(16, 64, 2), 128, ATTN_SMEM>>>(attn_w, out);
}

// round 15
// speedup vs baseline: 1.0707x; 1.0145x over previous
#include <cuda_runtime.h>
#include <cuda_bf16.h>
#include <cstdint>
#include <math.h>

// Problem constants: B=4, S=1024, D=1024, H=16, DH=64
// head-major scratch: [which(6)][b(4)][h(16)][s(1024)][d(64)], bf16 hi/lo split
__device__ __nv_bfloat16 g_qkv_hi[6ull * 4 * 16 * 1024 * 64];
__device__ __nv_bfloat16 g_qkv_lo[6ull * 4 * 16 * 1024 * 64];
// bf16 split GEMM operands
__device__ __nv_bfloat16 g_xhi[4096ull * 1024];
__device__ __nv_bfloat16 g_xlo[4096ull * 1024];
// W transposed to [which][n][k] so B tiles are K-major
__device__ __nv_bfloat16 g_wthi[6ull * 1024 * 1024];
__device__ __nv_bfloat16 g_wtlo[6ull * 1024 * 1024];

struct WPack {
    const float* W[6];
    const float* b[6];
};

// ---------------------------------------------------------------------------
// mma / ldmatrix / cp.async helpers (sm_80+ portable; target is sm_100)
// ---------------------------------------------------------------------------
__device__ __forceinline__ uint32_t smem_u32(const void* p) {
    uint32_t a;
    asm("{ .reg .u64 t; cvta.to.shared.u64 t, %1; cvt.u32.u64 %0, t; }" : "=r"(a) : "l"(p));
    return a;
}

#define LDSM_X4(r0, r1, r2, r3, addr) \
    asm volatile("ldmatrix.sync.aligned.m8n8.x4.shared.b16 {%0,%1,%2,%3}, [%4];" \
                 : "=r"(r0), "=r"(r1), "=r"(r2), "=r"(r3) : "r"(addr))
#define LDSM_X4_T(r0, r1, r2, r3, addr) \
    asm volatile("ldmatrix.sync.aligned.m8n8.x4.trans.shared.b16 {%0,%1,%2,%3}, [%4];" \
                 : "=r"(r0), "=r"(r1), "=r"(r2), "=r"(r3) : "r"(addr))

#define MMA_BF16(d, a, b0_, b1_) \
    asm volatile("mma.sync.aligned.m16n8k16.row.col.f32.bf16.bf16.f32 " \
                 "{%0,%1,%2,%3}, {%4,%5,%6,%7}, {%8,%9}, {%0,%1,%2,%3};" \
                 : "+f"((d)[0]), "+f"((d)[1]), "+f"((d)[2]), "+f"((d)[3]) \
                 : "r"((a)[0]), "r"((a)[1]), "r"((a)[2]), "r"((a)[3]), "r"(b0_), "r"(b1_))

#define CP_ASYNC16(dst, src) \
    asm volatile("cp.async.cg.shared.global [%0], [%1], 16;" :: "r"(dst), "l"(src) : "memory")
#define CP_COMMIT() asm volatile("cp.async.commit_group;" ::: "memory")
#define CP_WAIT(N)  asm volatile("cp.async.wait_group %0;" :: "n"(N) : "memory")

__device__ __forceinline__ uint32_t pack_bf16x2(float a, float b) {
    __nv_bfloat162 t = __floats2bfloat162_rn(a, b);
    return *reinterpret_cast<uint32_t*>(&t);
}

// 64-col bf16 tile (128B rows), XOR-chunk swizzle. col must be a multiple of 8.
__device__ __forceinline__ uint32_t swz64(int r, int col) {
    return (uint32_t)((r << 7) + ((((col >> 3) ^ (r & 7)) << 4)));
}

// ---------------------------------------------------------------------------
// Convert X -> bf16 hi/lo (x4 vectorized) + zero-fill output (same extent:
// both are 4M elements; fusing removes a launch).
// ---------------------------------------------------------------------------
__global__ __launch_bounds__(256) void convert_x_kernel(const float* __restrict__ x,
                                                        float* __restrict__ out)
{
    int i = (blockIdx.x * 256 + threadIdx.x) * 4;
    float4 v = *reinterpret_cast<const float4*>(x + i);
    float f[4] = {v.x, v.y, v.z, v.w};
    __nv_bfloat16 h[4];
    float l[4];
#pragma unroll
    for (int e = 0; e < 4; e++) {
        h[e] = __float2bfloat16(f[e]);
        l[e] = f[e] - __bfloat162float(h[e]);
    }
    __nv_bfloat162 h01; h01.x = h[0]; h01.y = h[1];
    __nv_bfloat162 h23; h23.x = h[2]; h23.y = h[3];
    uint2 hw = make_uint2(*reinterpret_cast<uint32_t*>(&h01), *reinterpret_cast<uint32_t*>(&h23));
    uint2 lw = make_uint2(pack_bf16x2(l[0], l[1]), pack_bf16x2(l[2], l[3]));
    *reinterpret_cast<uint2*>(g_xhi + i) = hw;
    *reinterpret_cast<uint2*>(g_xlo + i) = lw;
    *reinterpret_cast<float4*>(out + i) = make_float4(0.f, 0.f, 0.f, 0.f);
}

// ---------------------------------------------------------------------------
// Convert + transpose W[k][n] -> Wt[n][k] bf16 hi/lo
// ---------------------------------------------------------------------------
__global__ __launch_bounds__(256) void convert_w_kernel(WPack wp)
{
    __shared__ float tile[32][33];
    const int w = blockIdx.z;
    const int n0 = blockIdx.x * 32;
    const int k0 = blockIdx.y * 32;
    const float* __restrict__ W = wp.W[w];
    const int tx = threadIdx.x;   // 0..31
    const int ty = threadIdx.y;   // 0..7
#pragma unroll
    for (int i = 0; i < 4; i++) {
        int k = k0 + ty + i * 8;
        tile[ty + i * 8][tx] = W[(size_t)k * 1024 + n0 + tx];
    }
    __syncthreads();
#pragma unroll
    for (int i = 0; i < 4; i++) {
        int n = n0 + ty + i * 8;
        float v = tile[tx][ty + i * 8];
        __nv_bfloat16 hi = __float2bfloat16(v);
        __nv_bfloat16 lo = __float2bfloat16(v - __bfloat162float(hi));
        size_t off = (size_t)w * 1048576 + (size_t)n * 1024 + k0 + tx;
        g_wthi[off] = hi;
        g_wtlo[off] = lo;
    }
}

// ---------------------------------------------------------------------------
// HMMA projection GEMM — EXACT round-6 configuration (best measured):
// 256 thr, 8 warps (2x4), warp tile 64x32, 2-stage cp.async, issue AFTER
// compute, two barriers per iteration. smem 81920 B -> 2 CTAs/SM.
// ---------------------------------------------------------------------------
__global__ __launch_bounds__(256) void qkv_gemm_mma(WPack wp)
{
    extern __shared__ char dsm[];
    const uint32_t sb = smem_u32(dsm);

    const int tid = threadIdx.x;
    const int lane = tid & 31;
    const int wid = tid >> 5;
    const int wm = wid >> 2;        // 0..1  -> 64-row half
    const int wn = wid & 3;         // 0..3  -> 32-col quarter
    const int bn = blockIdx.x;      // 0..47
    const int bm = blockIdx.y;      // 0..31

    const __nv_bfloat16* __restrict__ ah = g_xhi + (size_t)(bm * 128) * 1024;
    const __nv_bfloat16* __restrict__ al = g_xlo + (size_t)(bm * 128) * 1024;
    const __nv_bfloat16* __restrict__ bhp = g_wthi + (size_t)(bn * 128) * 1024;
    const __nv_bfloat16* __restrict__ blp = g_wtlo + (size_t)(bn * 128) * 1024;

    auto issue = [&](int kb, int st) {
        uint32_t stb = sb + st * 40960;
#pragma unroll
        for (int uu = 0; uu < 2; uu++) {
            int idx = tid + uu * 256;           // 0..511
            int r = idx >> 2, c = idx & 3;
            size_t go = (size_t)r * 1024 + kb * 32 + c * 8;
            uint32_t so = (uint32_t)(r * 80 + c * 16);
            CP_ASYNC16(stb + so,          ah + go);
            CP_ASYNC16(stb + 10240 + so,  al + go);
            CP_ASYNC16(stb + 20480 + so,  bhp + go);
            CP_ASYNC16(stb + 30720 + so,  blp + go);
        }
    };

    float acc[4][4][4];
#pragma unroll
    for (int i = 0; i < 4; i++)
#pragma unroll
        for (int j = 0; j < 4; j++)
#pragma unroll
            for (int q = 0; q < 4; q++) acc[i][j][q] = 0.f;

    const int rsel = lane & 15;
    const int ksel = 8 * (lane >> 4);

    issue(0, 0); CP_COMMIT();
    issue(1, 1); CP_COMMIT();

    for (int kb = 0; kb < 32; kb++) {
        const int st = kb & 1;
        if (kb < 30) { CP_WAIT(1); } else { CP_WAIT(0); }
        __syncthreads();

        const uint32_t stb = sb + st * 40960;
#pragma unroll
        for (int ks = 0; ks < 2; ks++) {
            const uint32_t kk2 = (uint32_t)((ks * 16 + ksel) * 2);
            uint32_t bhf[4][2], blf[4][2];
#pragma unroll
            for (int np = 0; np < 2; np++) {
                uint32_t r0, r1, r2, r3;
                uint32_t adr = stb + 20480 + (uint32_t)((wn * 32 + np * 16 + rsel) * 80) + kk2;
                LDSM_X4(r0, r1, r2, r3, adr);
                bhf[2 * np][0] = r0; bhf[2 * np][1] = r2;
                bhf[2 * np + 1][0] = r1; bhf[2 * np + 1][1] = r3;
                LDSM_X4(r0, r1, r2, r3, adr + 10240);
                blf[2 * np][0] = r0; blf[2 * np][1] = r2;
                blf[2 * np + 1][0] = r1; blf[2 * np + 1][1] = r3;
            }
#pragma unroll
            for (int mt = 0; mt < 4; mt++) {
                uint32_t ahf[4], alf[4];
                uint32_t adr = stb + (uint32_t)((wm * 64 + mt * 16 + rsel) * 80) + kk2;
                LDSM_X4(ahf[0], ahf[1], ahf[2], ahf[3], adr);
                LDSM_X4(alf[0], alf[1], alf[2], alf[3], adr + 10240);
#pragma unroll
                for (int nt = 0; nt < 4; nt++) {
                    MMA_BF16(acc[mt][nt], ahf, bhf[nt][0], bhf[nt][1]);
                    MMA_BF16(acc[mt][nt], ahf, blf[nt][0], blf[nt][1]);
                    MMA_BF16(acc[mt][nt], alf, bhf[nt][0], bhf[nt][1]);
                }
            }
        }
        __syncthreads();
        if (kb + 2 < 32) { issue(kb + 2, st); CP_COMMIT(); }
    }

    // Epilogue: bias + bf16 hi/lo split, scattered to head-major layout
#pragma unroll
    for (int mt = 0; mt < 4; mt++) {
        int m0 = bm * 128 + wm * 64 + mt * 16 + (lane >> 2);
#pragma unroll
        for (int half = 0; half < 2; half++) {
            int m = m0 + half * 8;
            int bb = m >> 10, s = m & 1023;
#pragma unroll
            for (int nt = 0; nt < 4; nt++) {
                int ng = bn * 128 + wn * 32 + nt * 8 + 2 * (lane & 3);
                int which = ng >> 10, rem = ng & 1023;
                int hh = rem >> 6, d = rem & 63;
                float2 bias2 = *reinterpret_cast<const float2*>(wp.b[which] + rem);
                float v0 = acc[mt][nt][half * 2 + 0] + bias2.x;
                float v1 = acc[mt][nt][half * 2 + 1] + bias2.y;
                __nv_bfloat16 h0 = __float2bfloat16(v0);
                __nv_bfloat16 h1 = __float2bfloat16(v1);
                float l0 = v0 - __bfloat162float(h0);
                float l1 = v1 - __bfloat162float(h1);
                size_t off = (((size_t)which * 4 + bb) * 16 + hh) * 65536 + (size_t)s * 64 + d;
                __nv_bfloat162 hp; hp.x = h0; hp.y = h1;
                *reinterpret_cast<uint32_t*>(&g_qkv_hi[off]) = *reinterpret_cast<uint32_t*>(&hp);
                *reinterpret_cast<uint32_t*>(&g_qkv_lo[off]) = pack_bf16x2(l0, l1);
            }
        }
    }
}

// ---------------------------------------------------------------------------
// HMMA flash attention (round-6 geometry: q-tile 64, 4 warps, 2-stage
// cp.async). Both streams in ONE launch via grid.z; atomicAdd combine.
// __launch_bounds__(128, 3): cap regs at 168 so THREE 64KB-smem CTAs fit per
// SM (at 169 regs the 8-reg allocation granule rounds to 176 and blocks the
// third CTA -> measured occ 12.1%). 3 CTAs -> 12 warps/SM.
// Dynamic smem: 2 stages x {Kh,Kl,Vh,Vl} 64x64 bf16 swizzled = 65536 B.
// ---------------------------------------------------------------------------
__global__ __launch_bounds__(128, 3) void attn_mma(const float* __restrict__ attn_w,
                                                   float* __restrict__ out)
{
    extern __shared__ char dsm[];
    const uint32_t sb = smem_u32(dsm);

    const int tid = threadIdx.x;
    const int lane = tid & 31;
    const int warp = tid >> 5;
    const int qt = blockIdx.x;       // 0..15
    const int bhv = blockIdx.y;      // 0..63
    const int type = blockIdx.z;     // 0..1 (attention stream)
    const int b = bhv >> 4, h = bhv & 15;

    const size_t base = ((size_t)b * 16 + h) * 65536;
    const __nv_bfloat16* __restrict__ qh = g_qkv_hi + (size_t)(type * 3 + 0) * 4194304 + base;
    const __nv_bfloat16* __restrict__ ql = g_qkv_lo + (size_t)(type * 3 + 0) * 4194304 + base;
    const __nv_bfloat16* __restrict__ kh = g_qkv_hi + (size_t)(type * 3 + 1) * 4194304 + base;
    const __nv_bfloat16* __restrict__ kl = g_qkv_lo + (size_t)(type * 3 + 1) * 4194304 + base;
    const __nv_bfloat16* __restrict__ vh = g_qkv_hi + (size_t)(type * 3 + 2) * 4194304 + base;
    const __nv_bfloat16* __restrict__ vl = g_qkv_lo + (size_t)(type * 3 + 2) * 4194304 + base;

    const int rsel = lane & 15;
    const int ksel = 8 * (lane >> 4);

    // ---- stage Q through stage-0 K buffers via cp.async, grab Q fragments ----
#pragma unroll
    for (int u = 0; u < 4; u++) {
        int idx = tid + u * 128;            // 0..511
        int r = idx >> 3, c = idx & 7;
        size_t go = (size_t)(qt * 64 + r) * 64 + c * 8;
        uint32_t so = swz64(r, c * 8);
        CP_ASYNC16(sb + so,        qh + go);
        CP_ASYNC16(sb + 8192 + so, ql + go);
    }
    CP_COMMIT();
    CP_WAIT(0);
    __syncthreads();

    uint32_t qfh[4][4], qfl[4][4];
#pragma unroll
    for (int ks = 0; ks < 4; ks++) {
        int kk = ks * 16 + ksel;
        uint32_t adr = sb + swz64(warp * 16 + rsel, kk);
        LDSM_X4(qfh[ks][0], qfh[ks][1], qfh[ks][2], qfh[ks][3], adr);
        LDSM_X4(qfl[ks][0], qfl[ks][1], qfl[ks][2], qfl[ks][3], adr + 8192);
    }
    __syncthreads();   // all warps done reading stage 0 before K/V prefetch

    // K/V prefetch: per stage/array 64 rows x 8 chunks; 4 chunks/thread
    auto issue_kv = [&](int kt, int st) {
        uint32_t stb = sb + st * 32768;
#pragma unroll
        for (int u = 0; u < 4; u++) {
            int idx = tid + u * 128;
            int r = idx >> 3, c = idx & 7;
            size_t go = (size_t)(kt * 64 + r) * 64 + c * 8;
            uint32_t so = swz64(r, c * 8);
            CP_ASYNC16(stb + so,         kh + go);
            CP_ASYNC16(stb + 8192 + so,  kl + go);
            CP_ASYNC16(stb + 16384 + so, vh + go);
            CP_ASYNC16(stb + 24576 + so, vl + go);
        }
    };

    issue_kv(0, 0); CP_COMMIT();
    issue_kv(1, 1); CP_COMMIT();

    float o[8][4];
#pragma unroll
    for (int i = 0; i < 8; i++)
#pragma unroll
        for (int j = 0; j < 4; j++) o[i][j] = 0.f;
    float M0 = -1e30f, M1 = -1e30f, L0 = 0.f, L1 = 0.f;

    for (int kt = 0; kt < 16; kt++) {
        const int st = kt & 1;
        if (kt < 14) { CP_WAIT(1); } else { CP_WAIT(0); }
        __syncthreads();
        const uint32_t stb = sb + st * 32768;

        // ---- S = Q K^T (16 x 64), 3-way split ----
        float s[8][4];
#pragma unroll
        for (int i = 0; i < 8; i++)
#pragma unroll
            for (int j = 0; j < 4; j++) s[i][j] = 0.f;

#pragma unroll
        for (int ks = 0; ks < 4; ks++) {
            const int kk = ks * 16 + ksel;
            uint32_t bhf[8][2], blf[8][2];
#pragma unroll
            for (int np = 0; np < 4; np++) {
                uint32_t r0, r1, r2, r3;
                uint32_t adr = stb + swz64(np * 16 + rsel, kk);
                LDSM_X4(r0, r1, r2, r3, adr);
                bhf[2 * np][0] = r0; bhf[2 * np][1] = r2;
                bhf[2 * np + 1][0] = r1; bhf[2 * np + 1][1] = r3;
                LDSM_X4(r0, r1, r2, r3, adr + 8192);
                blf[2 * np][0] = r0; blf[2 * np][1] = r2;
                blf[2 * np + 1][0] = r1; blf[2 * np + 1][1] = r3;
            }
#pragma unroll
            for (int nt = 0; nt < 8; nt++) {
                MMA_BF16(s[nt], qfh[ks], bhf[nt][0], bhf[nt][1]);
                MMA_BF16(s[nt], qfh[ks], blf[nt][0], blf[nt][1]);
                MMA_BF16(s[nt], qfl[ks], bhf[nt][0], bhf[nt][1]);
            }
        }

        // ---- online softmax (rows: lane/4 and lane/4+8; quad-lane reduce) ----
        float rm0 = -1e30f, rm1 = -1e30f;
#pragma unroll
        for (int nt = 0; nt < 8; nt++) {
#pragma unroll
            for (int j = 0; j < 4; j++) s[nt][j] *= 0.125f;
            rm0 = fmaxf(rm0, fmaxf(s[nt][0], s[nt][1]));
            rm1 = fmaxf(rm1, fmaxf(s[nt][2], s[nt][3]));
        }
        rm0 = fmaxf(rm0, __shfl_xor_sync(0xffffffffu, rm0, 1));
        rm0 = fmaxf(rm0, __shfl_xor_sync(0xffffffffu, rm0, 2));
        rm1 = fmaxf(rm1, __shfl_xor_sync(0xffffffffu, rm1, 1));
        rm1 = fmaxf(rm1, __shfl_xor_sync(0xffffffffu, rm1, 2));
        float mn0 = fmaxf(M0, rm0), mn1 = fmaxf(M1, rm1);
        float sc0 = __expf(M0 - mn0), sc1 = __expf(M1 - mn1);
        float rs0 = 0.f, rs1 = 0.f;
#pragma unroll
        for (int nt = 0; nt < 8; nt++) {
            s[nt][0] = __expf(s[nt][0] - mn0);
            s[nt][1] = __expf(s[nt][1] - mn0);
            s[nt][2] = __expf(s[nt][2] - mn1);
            s[nt][3] = __expf(s[nt][3] - mn1);
            rs0 += s[nt][0] + s[nt][1];
            rs1 += s[nt][2] + s[nt][3];
        }
        rs0 += __shfl_xor_sync(0xffffffffu, rs0, 1);
        rs0 += __shfl_xor_sync(0xffffffffu, rs0, 2);
        rs1 += __shfl_xor_sync(0xffffffffu, rs1, 1);
        rs1 += __shfl_xor_sync(0xffffffffu, rs1, 2);
        L0 = L0 * sc0 + rs0; M0 = mn0;
        L1 = L1 * sc1 + rs1; M1 = mn1;
#pragma unroll
        for (int dt = 0; dt < 8; dt++) {
            o[dt][0] *= sc0; o[dt][1] *= sc0;
            o[dt][2] *= sc1; o[dt][3] *= sc1;
        }

        // ---- pack P (hi/lo) into A fragments: accum->A register identity ----
        uint32_t ph[4][4], pl[4][4];
#pragma unroll
        for (int kp = 0; kp < 4; kp++) {
            const int t0 = 2 * kp, t1 = 2 * kp + 1;
            float p_[8] = {s[t0][0], s[t0][1], s[t0][2], s[t0][3],
                           s[t1][0], s[t1][1], s[t1][2], s[t1][3]};
            __nv_bfloat16 hb[8];
            float lb[8];
#pragma unroll
            for (int e = 0; e < 8; e++) {
                hb[e] = __float2bfloat16(p_[e]);
                lb[e] = p_[e] - __bfloat162float(hb[e]);
            }
            __nv_bfloat162 t;
            t.x = hb[0]; t.y = hb[1]; ph[kp][0] = *reinterpret_cast<uint32_t*>(&t);
            t.x = hb[2]; t.y = hb[3]; ph[kp][1] = *reinterpret_cast<uint32_t*>(&t);
            t.x = hb[4]; t.y = hb[5]; ph[kp][2] = *reinterpret_cast<uint32_t*>(&t);
            t.x = hb[6]; t.y = hb[7]; ph[kp][3] = *reinterpret_cast<uint32_t*>(&t);
            pl[kp][0] = pack_bf16x2(lb[0], lb[1]);
            pl[kp][1] = pack_bf16x2(lb[2], lb[3]);
            pl[kp][2] = pack_bf16x2(lb[4], lb[5]);
            pl[kp][3] = pack_bf16x2(lb[6], lb[7]);
        }

        // ---- O += P V  (V^T fragments via ldmatrix.trans) ----
        const int krow = ((lane >> 4) * 8) + (lane & 7);
        const int dcol = ((lane >> 3) & 1) * 8;
#pragma unroll
        for (int ks = 0; ks < 4; ks++) {
            uint32_t vhf[8][2], vlf[8][2];
#pragma unroll
            for (int dp = 0; dp < 4; dp++) {
                uint32_t r0, r1, r2, r3;
                uint32_t adr = stb + 16384 + swz64(ks * 16 + krow, dp * 16 + dcol);
                LDSM_X4_T(r0, r1, r2, r3, adr);
                vhf[2 * dp][0] = r0; vhf[2 * dp][1] = r2;
                vhf[2 * dp + 1][0] = r1; vhf[2 * dp + 1][1] = r3;
                LDSM_X4_T(r0, r1, r2, r3, adr + 8192);
                vlf[2 * dp][0] = r0; vlf[2 * dp][1] = r2;
                vlf[2 * dp + 1][0] = r1; vlf[2 * dp + 1][1] = r3;
            }
#pragma unroll
            for (int dt = 0; dt < 8; dt++) {
                MMA_BF16(o[dt], ph[ks], vhf[dt][0], vhf[dt][1]);
                MMA_BF16(o[dt], ph[ks], vlf[dt][0], vlf[dt][1]);
                MMA_BF16(o[dt], pl[ks], vhf[dt][0], vhf[dt][1]);
            }
        }
        __syncthreads();
        if (kt + 2 < 16) { issue_kv(kt + 2, st); CP_COMMIT(); }
    }

    // ---- finalize: divide by L, apply stream weight, atomically accumulate ----
    float w0a = attn_w[0], w1a = attn_w[1];
    float mx = fmaxf(w0a, w1a);
    float e0 = __expf(w0a - mx), e1 = __expf(w1a - mx);
    float wA = ((type == 0) ? e0 : e1) / (e0 + e1);
    float i0 = wA / L0, i1 = wA / L1;

    const int r0 = qt * 64 + warp * 16 + (lane >> 2);
#pragma unroll
    for (int dt = 0; dt < 8; dt++) {
        int col = h * 64 + dt * 8 + 2 * (lane & 3);
        float* p0 = out + ((size_t)b * 1024 + r0) * 1024 + col;
        float* p1 = out + ((size_t)b * 1024 + r0 + 8) * 1024 + col;
        atomicAdd(p0 + 0, o[dt][0] * i0);
        atomicAdd(p0 + 1, o[dt][1] * i0);
        atomicAdd(p1 + 0, o[dt][2] * i1);
        atomicAdd(p1 + 1, o[dt][3] * i1);
    }
}

// ---------------------------------------------------------------------------
// Launch: convert_x(+zero) -> convert_w -> GEMM (r6 exact) -> attn (merged,
// now 3 CTAs/SM via launch_bounds).
// ---------------------------------------------------------------------------
extern "C" void kernel_launch(void* const* d_in, const int* in_sizes, int n_in,
                              void* d_out, int out_size)
{
    (void)in_sizes; (void)n_in; (void)out_size;
    const float* x = (const float*)d_in[0];
    WPack wp;
    for (int i = 0; i < 6; i++) {
        wp.W[i] = (const float*)d_in[1 + 2 * i];
        wp.b[i] = (const float*)d_in[2 + 2 * i];
    }
    const float* attn_w = (const float*)d_in[13];
    float* out = (float*)d_out;

    const int GEMM_SMEM = 81920;   // 2 stages x 4 arrays x 128x40 bf16 (2 CTAs/SM)
    const int ATTN_SMEM = 65536;   // 2 stages x 4 arrays x 64x64 bf16 (swizzled)
    cudaFuncSetAttribute(qkv_gemm_mma, cudaFuncAttributeMaxDynamicSharedMemorySize, GEMM_SMEM);
    cudaFuncSetAttribute(attn_mma, cudaFuncAttributeMaxDynamicSharedMemorySize, ATTN_SMEM);

    // 1) conversions; output zero-fill fused into convert_x
    convert_x_kernel<<<4096, 256>>>(x, out);
    convert_w_kernel<<<dim3(32, 32, 6), dim3(32, 8)>>>(wp);

    // 2) HMMA projection GEMM (exact round-6 configuration)
    qkv_gemm_mma<<<dim3(48, 32), 256, GEMM_SMEM>>>(wp);

    // 3) HMMA flash attention, both streams in one launch (grid.z = 2)
    attn_mma<<<dim3(16, 64, 2), 128, ATTN_SMEM>>>(attn_w, out);
}

// round 16
// speedup vs baseline: 1.1680x; 1.0909x over previous
#include <cuda_runtime.h>
#include <cuda_bf16.h>
#include <cstdint>
#include <math.h>

// Problem constants: B=4, S=1024, D=1024, H=16, DH=64
// head-major scratch: [which(6)][b(4)][h(16)][s(1024)][d(64)], bf16 hi/lo split
__device__ __nv_bfloat16 g_qkv_hi[6ull * 4 * 16 * 1024 * 64];
__device__ __nv_bfloat16 g_qkv_lo[6ull * 4 * 16 * 1024 * 64];
// bf16 split GEMM operands
__device__ __nv_bfloat16 g_xhi[4096ull * 1024];
__device__ __nv_bfloat16 g_xlo[4096ull * 1024];
// W transposed to [which][n][k] so B tiles are K-major
__device__ __nv_bfloat16 g_wthi[6ull * 1024 * 1024];
__device__ __nv_bfloat16 g_wtlo[6ull * 1024 * 1024];

struct WPack {
    const float* W[6];
    const float* b[6];
};

// ---------------------------------------------------------------------------
// mma / ldmatrix / cp.async helpers (sm_80+ portable; target is sm_100)
// ---------------------------------------------------------------------------
__device__ __forceinline__ uint32_t smem_u32(const void* p) {
    uint32_t a;
    asm("{ .reg .u64 t; cvta.to.shared.u64 t, %1; cvt.u32.u64 %0, t; }" : "=r"(a) : "l"(p));
    return a;
}

#define LDSM_X4(r0, r1, r2, r3, addr) \
    asm volatile("ldmatrix.sync.aligned.m8n8.x4.shared.b16 {%0,%1,%2,%3}, [%4];" \
                 : "=r"(r0), "=r"(r1), "=r"(r2), "=r"(r3) : "r"(addr))
#define LDSM_X4_T(r0, r1, r2, r3, addr) \
    asm volatile("ldmatrix.sync.aligned.m8n8.x4.trans.shared.b16 {%0,%1,%2,%3}, [%4];" \
                 : "=r"(r0), "=r"(r1), "=r"(r2), "=r"(r3) : "r"(addr))

#define MMA_BF16(d, a, b0_, b1_) \
    asm volatile("mma.sync.aligned.m16n8k16.row.col.f32.bf16.bf16.f32 " \
                 "{%0,%1,%2,%3}, {%4,%5,%6,%7}, {%8,%9}, {%0,%1,%2,%3};" \
                 : "+f"((d)[0]), "+f"((d)[1]), "+f"((d)[2]), "+f"((d)[3]) \
                 : "r"((a)[0]), "r"((a)[1]), "r"((a)[2]), "r"((a)[3]), "r"(b0_), "r"(b1_))

#define CP_ASYNC16(dst, src) \
    asm volatile("cp.async.cg.shared.global [%0], [%1], 16;" :: "r"(dst), "l"(src) : "memory")
#define CP_COMMIT() asm volatile("cp.async.commit_group;" ::: "memory")
#define CP_WAIT(N)  asm volatile("cp.async.wait_group %0;" :: "n"(N) : "memory")

__device__ __forceinline__ uint32_t pack_bf16x2(float a, float b) {
    __nv_bfloat162 t = __floats2bfloat162_rn(a, b);
    return *reinterpret_cast<uint32_t*>(&t);
}

// 64-col bf16 tile (128B rows), XOR-chunk swizzle. col must be a multiple of 8.
__device__ __forceinline__ uint32_t swz64(int r, int col) {
    return (uint32_t)((r << 7) + ((((col >> 3) ^ (r & 7)) << 4)));
}

// GEMM tile swizzle: 128 rows x 32 cols bf16 (64B/row) packed as 64 fat rows
// of 128B (rows 2f and 2f+1). chunk_in_fat = ((r&1)*4 + cc) ^ (f & 7).
// Conflict-free for both cp.async (32 distinct chunks/warp) and ldmatrix
// (each 8-lane phase hits 8 distinct chunks). cc = col/8 in [0,4).
__device__ __forceinline__ uint32_t swzg(int r, int cc) {
    return (uint32_t)(((r >> 1) << 7) +
                      ((((((r & 1) << 2) + cc) ^ ((r >> 1) & 7))) << 4));
}

// ---------------------------------------------------------------------------
// Convert X -> bf16 hi/lo (x4 vectorized) + zero-fill output.
// ---------------------------------------------------------------------------
__global__ __launch_bounds__(256) void convert_x_kernel(const float* __restrict__ x,
                                                        float* __restrict__ out)
{
    int i = (blockIdx.x * 256 + threadIdx.x) * 4;
    float4 v = *reinterpret_cast<const float4*>(x + i);
    float f[4] = {v.x, v.y, v.z, v.w};
    __nv_bfloat16 h[4];
    float l[4];
#pragma unroll
    for (int e = 0; e < 4; e++) {
        h[e] = __float2bfloat16(f[e]);
        l[e] = f[e] - __bfloat162float(h[e]);
    }
    __nv_bfloat162 h01; h01.x = h[0]; h01.y = h[1];
    __nv_bfloat162 h23; h23.x = h[2]; h23.y = h[3];
    uint2 hw = make_uint2(*reinterpret_cast<uint32_t*>(&h01), *reinterpret_cast<uint32_t*>(&h23));
    uint2 lw = make_uint2(pack_bf16x2(l[0], l[1]), pack_bf16x2(l[2], l[3]));
    *reinterpret_cast<uint2*>(g_xhi + i) = hw;
    *reinterpret_cast<uint2*>(g_xlo + i) = lw;
    *reinterpret_cast<float4*>(out + i) = make_float4(0.f, 0.f, 0.f, 0.f);
}

// ---------------------------------------------------------------------------
// Convert + transpose W[k][n] -> Wt[n][k] bf16 hi/lo
// ---------------------------------------------------------------------------
__global__ __launch_bounds__(256) void convert_w_kernel(WPack wp)
{
    __shared__ float tile[32][33];
    const int w = blockIdx.z;
    const int n0 = blockIdx.x * 32;
    const int k0 = blockIdx.y * 32;
    const float* __restrict__ W = wp.W[w];
    const int tx = threadIdx.x;   // 0..31
    const int ty = threadIdx.y;   // 0..7
#pragma unroll
    for (int i = 0; i < 4; i++) {
        int k = k0 + ty + i * 8;
        tile[ty + i * 8][tx] = W[(size_t)k * 1024 + n0 + tx];
    }
    __syncthreads();
#pragma unroll
    for (int i = 0; i < 4; i++) {
        int n = n0 + ty + i * 8;
        float v = tile[tx][ty + i * 8];
        __nv_bfloat16 hi = __float2bfloat16(v);
        __nv_bfloat16 lo = __float2bfloat16(v - __bfloat162float(hi));
        size_t off = (size_t)w * 1048576 + (size_t)n * 1024 + k0 + tx;
        g_wthi[off] = hi;
        g_wtlo[off] = lo;
    }
}

// ---------------------------------------------------------------------------
// HMMA projection GEMM — r6 warp geometry (256 thr, 8 warps 2x4, warp tile
// 64x32) with a 3-STAGE single-barrier pipeline at 2 CTAs/SM, enabled by the
// pad-free fat-row swizzle (8192 B/array/stage; 3 stages x 32768 = 98304 B).
// Loop: CP_WAIT -> sync -> issue(kb+2) -> compute. Buffer (kb+2)%3 ==
// (kb-1)%3, whose readers all passed the barrier.
// ---------------------------------------------------------------------------
__global__ __launch_bounds__(256) void qkv_gemm_mma(WPack wp)
{
    extern __shared__ char dsm[];
    const uint32_t sb = smem_u32(dsm);

    const int tid = threadIdx.x;
    const int lane = tid & 31;
    const int wid = tid >> 5;
    const int wm = wid >> 2;        // 0..1  -> 64-row half
    const int wn = wid & 3;         // 0..3  -> 32-col quarter
    const int bn = blockIdx.x;      // 0..47
    const int bm = blockIdx.y;      // 0..31

    const __nv_bfloat16* __restrict__ ah = g_xhi + (size_t)(bm * 128) * 1024;
    const __nv_bfloat16* __restrict__ al = g_xlo + (size_t)(bm * 128) * 1024;
    const __nv_bfloat16* __restrict__ bhp = g_wthi + (size_t)(bn * 128) * 1024;
    const __nv_bfloat16* __restrict__ blp = g_wtlo + (size_t)(bn * 128) * 1024;

    // per stage/array: 128 rows x 4 chunks of 16B = 512 chunks; 2/thread
    auto issue = [&](int kb, int st) {
        uint32_t stb = sb + st * 32768;
#pragma unroll
        for (int uu = 0; uu < 2; uu++) {
            int idx = tid + uu * 256;           // 0..511
            int r = idx >> 2, c = idx & 3;
            size_t go = (size_t)r * 1024 + kb * 32 + c * 8;
            uint32_t so = swzg(r, c);
            CP_ASYNC16(stb + so,          ah + go);
            CP_ASYNC16(stb + 8192 + so,   al + go);
            CP_ASYNC16(stb + 16384 + so,  bhp + go);
            CP_ASYNC16(stb + 24576 + so,  blp + go);
        }
    };

    float acc[4][4][4];
#pragma unroll
    for (int i = 0; i < 4; i++)
#pragma unroll
        for (int j = 0; j < 4; j++)
#pragma unroll
            for (int q = 0; q < 4; q++) acc[i][j][q] = 0.f;

    const int rsel = lane & 15;
    const int csel = lane >> 4;      // 0/1 -> column chunk within 16-col step

    issue(0, 0); CP_COMMIT();
    issue(1, 1); CP_COMMIT();

    for (int kb = 0; kb < 32; kb++) {
        const int st = kb % 3;
        if (kb < 31) { CP_WAIT(1); } else { CP_WAIT(0); }
        __syncthreads();
        if (kb + 2 < 32) { issue(kb + 2, (kb + 2) % 3); CP_COMMIT(); }

        const uint32_t stb = sb + st * 32768;
#pragma unroll
        for (int ks = 0; ks < 2; ks++) {
            const int cc = ks * 2 + csel;    // chunk index 0..3
            uint32_t bhf[4][2], blf[4][2];
#pragma unroll
            for (int np = 0; np < 2; np++) {
                uint32_t r0, r1, r2, r3;
                uint32_t adr = stb + 16384 + swzg(wn * 32 + np * 16 + rsel, cc);
                LDSM_X4(r0, r1, r2, r3, adr);
                bhf[2 * np][0] = r0; bhf[2 * np][1] = r2;
                bhf[2 * np + 1][0] = r1; bhf[2 * np + 1][1] = r3;
                adr = stb + 24576 + swzg(wn * 32 + np * 16 + rsel, cc);
                LDSM_X4(r0, r1, r2, r3, adr);
                blf[2 * np][0] = r0; blf[2 * np][1] = r2;
                blf[2 * np + 1][0] = r1; blf[2 * np + 1][1] = r3;
            }
#pragma unroll
            for (int mt = 0; mt < 4; mt++) {
                uint32_t ahf[4], alf[4];
                uint32_t adr = stb + swzg(wm * 64 + mt * 16 + rsel, cc);
                LDSM_X4(ahf[0], ahf[1], ahf[2], ahf[3], adr);
                adr = stb + 8192 + swzg(wm * 64 + mt * 16 + rsel, cc);
                LDSM_X4(alf[0], alf[1], alf[2], alf[3], adr);
#pragma unroll
                for (int nt = 0; nt < 4; nt++) {
                    MMA_BF16(acc[mt][nt], ahf, bhf[nt][0], bhf[nt][1]);
                    MMA_BF16(acc[mt][nt], ahf, blf[nt][0], blf[nt][1]);
                    MMA_BF16(acc[mt][nt], alf, bhf[nt][0], bhf[nt][1]);
                }
            }
        }
    }

    // Epilogue: bias + bf16 hi/lo split, scattered to head-major layout
#pragma unroll
    for (int mt = 0; mt < 4; mt++) {
        int m0 = bm * 128 + wm * 64 + mt * 16 + (lane >> 2);
#pragma unroll
        for (int half = 0; half < 2; half++) {
            int m = m0 + half * 8;
            int bb = m >> 10, s = m & 1023;
#pragma unroll
            for (int nt = 0; nt < 4; nt++) {
                int ng = bn * 128 + wn * 32 + nt * 8 + 2 * (lane & 3);
                int which = ng >> 10, rem = ng & 1023;
                int hh = rem >> 6, d = rem & 63;
                float2 bias2 = *reinterpret_cast<const float2*>(wp.b[which] + rem);
                float v0 = acc[mt][nt][half * 2 + 0] + bias2.x;
                float v1 = acc[mt][nt][half * 2 + 1] + bias2.y;
                __nv_bfloat16 h0 = __float2bfloat16(v0);
                __nv_bfloat16 h1 = __float2bfloat16(v1);
                float l0 = v0 - __bfloat162float(h0);
                float l1 = v1 - __bfloat162float(h1);
                size_t off = (((size_t)which * 4 + bb) * 16 + hh) * 65536 + (size_t)s * 64 + d;
                __nv_bfloat162 hp; hp.x = h0; hp.y = h1;
                *reinterpret_cast<uint32_t*>(&g_qkv_hi[off]) = *reinterpret_cast<uint32_t*>(&hp);
                *reinterpret_cast<uint32_t*>(&g_qkv_lo[off]) = pack_bf16x2(l0, l1);
            }
        }
    }
}

// ---------------------------------------------------------------------------
// HMMA flash attention (round-15 exact: q-tile 64, 4 warps, 2-stage cp.async,
// merged streams via grid.z, atomicAdd combine, __launch_bounds__(128,3) to
// hold 168 regs -> 3 CTAs/SM).
// ---------------------------------------------------------------------------
__global__ __launch_bounds__(128, 3) void attn_mma(const float* __restrict__ attn_w,
                                                   float* __restrict__ out)
{
    extern __shared__ char dsm[];
    const uint32_t sb = smem_u32(dsm);

    const int tid = threadIdx.x;
    const int lane = tid & 31;
    const int warp = tid >> 5;
    const int qt = blockIdx.x;       // 0..15
    const int bhv = blockIdx.y;      // 0..63
    const int type = blockIdx.z;     // 0..1 (attention stream)
    const int b = bhv >> 4, h = bhv & 15;

    const size_t base = ((size_t)b * 16 + h) * 65536;
    const __nv_bfloat16* __restrict__ qh = g_qkv_hi + (size_t)(type * 3 + 0) * 4194304 + base;
    const __nv_bfloat16* __restrict__ ql = g_qkv_lo + (size_t)(type * 3 + 0) * 4194304 + base;
    const __nv_bfloat16* __restrict__ kh = g_qkv_hi + (size_t)(type * 3 + 1) * 4194304 + base;
    const __nv_bfloat16* __restrict__ kl = g_qkv_lo + (size_t)(type * 3 + 1) * 4194304 + base;
    const __nv_bfloat16* __restrict__ vh = g_qkv_hi + (size_t)(type * 3 + 2) * 4194304 + base;
    const __nv_bfloat16* __restrict__ vl = g_qkv_lo + (size_t)(type * 3 + 2) * 4194304 + base;

    const int rsel = lane & 15;
    const int ksel = 8 * (lane >> 4);

    // ---- stage Q through stage-0 K buffers via cp.async, grab Q fragments ----
#pragma unroll
    for (int u = 0; u < 4; u++) {
        int idx = tid + u * 128;            // 0..511
        int r = idx >> 3, c = idx & 7;
        size_t go = (size_t)(qt * 64 + r) * 64 + c * 8;
        uint32_t so = swz64(r, c * 8);
        CP_ASYNC16(sb + so,        qh + go);
        CP_ASYNC16(sb + 8192 + so, ql + go);
    }
    CP_COMMIT();
    CP_WAIT(0);
    __syncthreads();

    uint32_t qfh[4][4], qfl[4][4];
#pragma unroll
    for (int ks = 0; ks < 4; ks++) {
        int kk = ks * 16 + ksel;
        uint32_t adr = sb + swz64(warp * 16 + rsel, kk);
        LDSM_X4(qfh[ks][0], qfh[ks][1], qfh[ks][2], qfh[ks][3], adr);
        LDSM_X4(qfl[ks][0], qfl[ks][1], qfl[ks][2], qfl[ks][3], adr + 8192);
    }
    __syncthreads();   // all warps done reading stage 0 before K/V prefetch

    // K/V prefetch: per stage/array 64 rows x 8 chunks; 4 chunks/thread
    auto issue_kv = [&](int kt, int st) {
        uint32_t stb = sb + st * 32768;
#pragma unroll
        for (int u = 0; u < 4; u++) {
            int idx = tid + u * 128;
            int r = idx >> 3, c = idx & 7;
            size_t go = (size_t)(kt * 64 + r) * 64 + c * 8;
            uint32_t so = swz64(r, c * 8);
            CP_ASYNC16(stb + so,         kh + go);
            CP_ASYNC16(stb + 8192 + so,  kl + go);
            CP_ASYNC16(stb + 16384 + so, vh + go);
            CP_ASYNC16(stb + 24576 + so, vl + go);
        }
    };

    issue_kv(0, 0); CP_COMMIT();
    issue_kv(1, 1); CP_COMMIT();

    float o[8][4];
#pragma unroll
    for (int i = 0; i < 8; i++)
#pragma unroll
        for (int j = 0; j < 4; j++) o[i][j] = 0.f;
    float M0 = -1e30f, M1 = -1e30f, L0 = 0.f, L1 = 0.f;

    for (int kt = 0; kt < 16; kt++) {
        const int st = kt & 1;
        if (kt < 14) { CP_WAIT(1); } else { CP_WAIT(0); }
        __syncthreads();
        const uint32_t stb = sb + st * 32768;

        // ---- S = Q K^T (16 x 64), 3-way split ----
        float s[8][4];
#pragma unroll
        for (int i = 0; i < 8; i++)
#pragma unroll
            for (int j = 0; j < 4; j++) s[i][j] = 0.f;

#pragma unroll
        for (int ks = 0; ks < 4; ks++) {
            const int kk = ks * 16 + ksel;
            uint32_t bhf[8][2], blf[8][2];
#pragma unroll
            for (int np = 0; np < 4; np++) {
                uint32_t r0, r1, r2, r3;
                uint32_t adr = stb + swz64(np * 16 + rsel, kk);
                LDSM_X4(r0, r1, r2, r3, adr);
                bhf[2 * np][0] = r0; bhf[2 * np][1] = r2;
                bhf[2 * np + 1][0] = r1; bhf[2 * np + 1][1] = r3;
                LDSM_X4(r0, r1, r2, r3, adr + 8192);
                blf[2 * np][0] = r0; blf[2 * np][1] = r2;
                blf[2 * np + 1][0] = r1; blf[2 * np + 1][1] = r3;
            }
#pragma unroll
            for (int nt = 0; nt < 8; nt++) {
                MMA_BF16(s[nt], qfh[ks], bhf[nt][0], bhf[nt][1]);
                MMA_BF16(s[nt], qfh[ks], blf[nt][0], blf[nt][1]);
                MMA_BF16(s[nt], qfl[ks], bhf[nt][0], bhf[nt][1]);
            }
        }

        // ---- online softmax (rows: lane/4 and lane/4+8; quad-lane reduce) ----
        float rm0 = -1e30f, rm1 = -1e30f;
#pragma unroll
        for (int nt = 0; nt < 8; nt++) {
#pragma unroll
            for (int j = 0; j < 4; j++) s[nt][j] *= 0.125f;
            rm0 = fmaxf(rm0, fmaxf(s[nt][0], s[nt][1]));
            rm1 = fmaxf(rm1, fmaxf(s[nt][2], s[nt][3]));
        }
        rm0 = fmaxf(rm0, __shfl_xor_sync(0xffffffffu, rm0, 1));
        rm0 = fmaxf(rm0, __shfl_xor_sync(0xffffffffu, rm0, 2));
        rm1 = fmaxf(rm1, __shfl_xor_sync(0xffffffffu, rm1, 1));
        rm1 = fmaxf(rm1, __shfl_xor_sync(0xffffffffu, rm1, 2));
        float mn0 = fmaxf(M0, rm0), mn1 = fmaxf(M1, rm1);
        float sc0 = __expf(M0 - mn0), sc1 = __expf(M1 - mn1);
        float rs0 = 0.f, rs1 = 0.f;
#pragma unroll
        for (int nt = 0; nt < 8; nt++) {
            s[nt][0] = __expf(s[nt][0] - mn0);
            s[nt][1] = __expf(s[nt][1] - mn0);
            s[nt][2] = __expf(s[nt][2] - mn1);
            s[nt][3] = __expf(s[nt][3] - mn1);
            rs0 += s[nt][0] + s[nt][1];
            rs1 += s[nt][2] + s[nt][3];
        }
        rs0 += __shfl_xor_sync(0xffffffffu, rs0, 1);
        rs0 += __shfl_xor_sync(0xffffffffu, rs0, 2);
        rs1 += __shfl_xor_sync(0xffffffffu, rs1, 1);
        rs1 += __shfl_xor_sync(0xffffffffu, rs1, 2);
        L0 = L0 * sc0 + rs0; M0 = mn0;
        L1 = L1 * sc1 + rs1; M1 = mn1;
#pragma unroll
        for (int dt = 0; dt < 8; dt++) {
            o[dt][0] *= sc0; o[dt][1] *= sc0;
            o[dt][2] *= sc1; o[dt][3] *= sc1;
        }

        // ---- pack P (hi/lo) into A fragments: accum->A register identity ----
        uint32_t ph[4][4], pl[4][4];
#pragma unroll
        for (int kp = 0; kp < 4; kp++) {
            const int t0 = 2 * kp, t1 = 2 * kp + 1;
            float p_[8] = {s[t0][0], s[t0][1], s[t0][2], s[t0][3],
                           s[t1][0], s[t1][1], s[t1][2], s[t1][3]};
            __nv_bfloat16 hb[8];
            float lb[8];
#pragma unroll
            for (int e = 0; e < 8; e++) {
                hb[e] = __float2bfloat16(p_[e]);
                lb[e] = p_[e] - __bfloat162float(hb[e]);
            }
            __nv_bfloat162 t;
            t.x = hb[0]; t.y = hb[1]; ph[kp][0] = *reinterpret_cast<uint32_t*>(&t);
            t.x = hb[2]; t.y = hb[3]; ph[kp][1] = *reinterpret_cast<uint32_t*>(&t);
            t.x = hb[4]; t.y = hb[5]; ph[kp][2] = *reinterpret_cast<uint32_t*>(&t);
            t.x = hb[6]; t.y = hb[7]; ph[kp][3] = *reinterpret_cast<uint32_t*>(&t);
            pl[kp][0] = pack_bf16x2(lb[0], lb[1]);
            pl[kp][1] = pack_bf16x2(lb[2], lb[3]);
            pl[kp][2] = pack_bf16x2(lb[4], lb[5]);
            pl[kp][3] = pack_bf16x2(lb[6], lb[7]);
        }

        // ---- O += P V  (V^T fragments via ldmatrix.trans) ----
        const int krow = ((lane >> 4) * 8) + (lane & 7);
        const int dcol = ((lane >> 3) & 1) * 8;
#pragma unroll
        for (int ks = 0; ks < 4; ks++) {
            uint32_t vhf[8][2], vlf[8][2];
#pragma unroll
            for (int dp = 0; dp < 4; dp++) {
                uint32_t r0, r1, r2, r3;
                uint32_t adr = stb + 16384 + swz64(ks * 16 + krow, dp * 16 + dcol);
                LDSM_X4_T(r0, r1, r2, r3, adr);
                vhf[2 * dp][0] = r0; vhf[2 * dp][1] = r2;
                vhf[2 * dp + 1][0] = r1; vhf[2 * dp + 1][1] = r3;
                LDSM_X4_T(r0, r1, r2, r3, adr + 8192);
                vlf[2 * dp][0] = r0; vlf[2 * dp][1] = r2;
                vlf[2 * dp + 1][0] = r1; vlf[2 * dp + 1][1] = r3;
            }
#pragma unroll
            for (int dt = 0; dt < 8; dt++) {
                MMA_BF16(o[dt], ph[ks], vhf[dt][0], vhf[dt][1]);
                MMA_BF16(o[dt], ph[ks], vlf[dt][0], vlf[dt][1]);
                MMA_BF16(o[dt], pl[ks], vhf[dt][0], vhf[dt][1]);
            }
        }
        __syncthreads();
        if (kt + 2 < 16) { issue_kv(kt + 2, st); CP_COMMIT(); }
    }

    // ---- finalize: divide by L, apply stream weight, atomically accumulate ----
    float w0a = attn_w[0], w1a = attn_w[1];
    float mx = fmaxf(w0a, w1a);
    float e0 = __expf(w0a - mx), e1 = __expf(w1a - mx);
    float wA = ((type == 0) ? e0 : e1) / (e0 + e1);
    float i0 = wA / L0, i1 = wA / L1;

    const int r0 = qt * 64 + warp * 16 + (lane >> 2);
#pragma unroll
    for (int dt = 0; dt < 8; dt++) {
        int col = h * 64 + dt * 8 + 2 * (lane & 3);
        float* p0 = out + ((size_t)b * 1024 + r0) * 1024 + col;
        float* p1 = out + ((size_t)b * 1024 + r0 + 8) * 1024 + col;
        atomicAdd(p0 + 0, o[dt][0] * i0);
        atomicAdd(p0 + 1, o[dt][1] * i0);
        atomicAdd(p1 + 0, o[dt][2] * i1);
        atomicAdd(p1 + 1, o[dt][3] * i1);
    }
}

// ---------------------------------------------------------------------------
// Launch: convert_x(+zero) -> convert_w -> GEMM (3-stage, fat-row swizzle)
// -> attn (merged, 3 CTAs/SM).
// ---------------------------------------------------------------------------
extern "C" void kernel_launch(void* const* d_in, const int* in_sizes, int n_in,
                              void* d_out, int out_size)
{
    (void)in_sizes; (void)n_in; (void)out_size;
    const float* x = (const float*)d_in[0];
    WPack wp;
    for (int i = 0; i < 6; i++) {
        wp.W[i] = (const float*)d_in[1 + 2 * i];
        wp.b[i] = (const float*)d_in[2 + 2 * i];
    }
    const float* attn_w = (const float*)d_in[13];
    float* out = (float*)d_out;

    const int GEMM_SMEM = 98304;   // 3 stages x 4 arrays x 8192 B (2 CTAs/SM)
    const int ATTN_SMEM = 65536;   // 2 stages x 4 arrays x 64x64 bf16 (swizzled)
    cudaFuncSetAttribute(qkv_gemm_mma, cudaFuncAttributeMaxDynamicSharedMemorySize, GEMM_SMEM);
    cudaFuncSetAttribute(attn_mma, cudaFuncAttributeMaxDynamicSharedMemorySize, ATTN_SMEM);

    // 1) conversions; output zero-fill fused into convert_x
    convert_x_kernel<<<4096, 256>>>(x, out);
    convert_w_kernel<<<dim3(32, 32, 6), dim3(32, 8)>>>(wp);

    // 2) HMMA projection GEMM (3-stage single-barrier pipeline, 2 CTAs/SM)
    qkv_gemm_mma<<<dim3(48, 32), 256, GEMM_SMEM>>>(wp);

    // 3) HMMA flash attention, both streams in one launch (grid.z = 2)
    attn_mma<<<dim3(16, 64, 2), 128, ATTN_SMEM>>>(attn_w, out);
}